// round 14
// baseline (speedup 1.0000x reference)
#include <cuda_runtime.h>
#include <cuda_bf16.h>
#include <math.h>
#include <stdint.h>

// Problem constants
#define N_NODES 50000
#define IN_C    512
#define HDIM    256   // H*HID
#define H2DIM   160   // H*OUT_C
#define OUT_C   40
#define MAXE    400000
#define MBLK    391   // ceil(50000/128)
#define MBLK0   196   // first half of row blocks (196*128 = 25088 rows)
#define NSPLIT  25088 // node split aligned to 128

// ---------------------------------------------------------------------------
// Scratch (static device globals)
// ---------------------------------------------------------------------------
__device__ float g_h1[(size_t)N_NODES * HDIM];
__device__ float g_h2[(size_t)N_NODES * H2DIM];
__device__ __align__(16) __nv_bfloat16 g_a1_hi[(size_t)N_NODES * HDIM];
__device__ __align__(16) __nv_bfloat16 g_a1_lo[(size_t)N_NODES * HDIM];
__device__ __align__(16) __nv_bfloat16 g_w1t_hi[(size_t)HDIM * IN_C];   // [n][k]
__device__ __align__(16) __nv_bfloat16 g_w1t_lo[(size_t)HDIM * IN_C];
__device__ __align__(16) __nv_bfloat16 g_w2t_hi[(size_t)H2DIM * HDIM];  // [n][k]
__device__ __align__(16) __nv_bfloat16 g_w2t_lo[(size_t)H2DIM * HDIM];
__device__ int g_cnt[N_NODES];
__device__ int g_rowptr[N_NODES + 1];
__device__ int g_wptr[N_NODES];
__device__ int g_csrsrc[MAXE + N_NODES];

// ---------------------------------------------------------------------------
// mma.sync bf16 + ldmatrix + cp.async helpers (family-common ISA)
// ---------------------------------------------------------------------------
__device__ __forceinline__ void mma_bf16(float* d, const uint32_t* a, const uint32_t* b) {
    asm volatile(
        "mma.sync.aligned.m16n8k16.row.col.f32.bf16.bf16.f32 "
        "{%0,%1,%2,%3}, {%4,%5,%6,%7}, {%8,%9}, {%0,%1,%2,%3};"
        : "+f"(d[0]), "+f"(d[1]), "+f"(d[2]), "+f"(d[3])
        : "r"(a[0]), "r"(a[1]), "r"(a[2]), "r"(a[3]), "r"(b[0]), "r"(b[1]));
}
__device__ __forceinline__ void ldsm_x4(uint32_t* r, uint32_t addr) {
    asm volatile("ldmatrix.sync.aligned.m8n8.x4.shared.b16 {%0,%1,%2,%3}, [%4];"
        : "=r"(r[0]), "=r"(r[1]), "=r"(r[2]), "=r"(r[3]) : "r"(addr));
}
__device__ __forceinline__ void ldsm_x2(uint32_t* r, uint32_t addr) {
    asm volatile("ldmatrix.sync.aligned.m8n8.x2.shared.b16 {%0,%1}, [%2];"
        : "=r"(r[0]), "=r"(r[1]) : "r"(addr));
}
__device__ __forceinline__ uint32_t smem_u32(const void* p) {
    uint32_t a;
    asm("{ .reg .u64 t; cvta.to.shared.u64 t, %1; cvt.u32.u64 %0, t; }" : "=r"(a) : "l"(p));
    return a;
}
#define CP_ASYNC16(dst, src) \
    asm volatile("cp.async.cg.shared.global [%0], [%1], 16;" :: "r"(dst), "l"(src))
#define CP_COMMIT()  asm volatile("cp.async.commit_group;" ::: "memory")
#define CP_WAIT(n)   asm volatile("cp.async.wait_group %0;" :: "n"(n) : "memory")

__device__ __forceinline__ uint32_t cvt_bf16x2(float hi_elem, float lo_elem) {
    uint32_t r;
    asm("cvt.rn.bf16x2.f32 %0, %1, %2;" : "=r"(r) : "f"(hi_elem), "f"(lo_elem));
    return r;
}

// ---------------------------------------------------------------------------
// Fused weight prep: transpose + bf16 split for W1 and W2 in one launch.
// ---------------------------------------------------------------------------
__global__ void k_prep_w(const float* __restrict__ W1, const float* __restrict__ W2) {
    int idx = blockIdx.x * blockDim.x + threadIdx.x;
    const int N1 = IN_C * HDIM;
    if (idx < N1) {
        int k = idx / HDIM, n = idx % HDIM;
        float v = W1[idx];
        __nv_bfloat16 h = __float2bfloat16(v);
        g_w1t_hi[(size_t)n * IN_C + k] = h;
        g_w1t_lo[(size_t)n * IN_C + k] = __float2bfloat16(v - __bfloat162float(h));
    } else if (idx < N1 + HDIM * H2DIM) {
        int j = idx - N1;
        int k = j / H2DIM, n = j % H2DIM;
        float v = W2[j];
        __nv_bfloat16 h = __float2bfloat16(v);
        g_w2t_hi[(size_t)n * HDIM + k] = h;
        g_w2t_lo[(size_t)n * HDIM + k] = __float2bfloat16(v - __bfloat162float(h));
    }
}

// ---------------------------------------------------------------------------
// CSR construction (+ output tail zeroing folded into init)
// ---------------------------------------------------------------------------
__global__ void k_init_cnt(float* out, int out_size) {
    int i = blockIdx.x * blockDim.x + threadIdx.x;
    if (i < N_NODES) g_cnt[i] = 1;
    if (blockIdx.x == 0) {
        for (int j = N_NODES * OUT_C + threadIdx.x; j < out_size; j += blockDim.x)
            out[j] = 0.f;
    }
}
__global__ void k_hist(const int* __restrict__ ei, int E) {
    int e = blockIdx.x * blockDim.x + threadIdx.x;
    if (e < E) {
        int d = ei[E + e];
        if ((unsigned)d < (unsigned)N_NODES) atomicAdd(&g_cnt[d], 1);
    }
}

__global__ void k_scan(int n) {
    __shared__ int wsum[32];
    __shared__ int s_carry;
    const int tid = threadIdx.x;
    const int lane = tid & 31, wrp = tid >> 5;
    if (tid == 0) s_carry = 0;
    __syncthreads();
    for (int base = 0; base < n; base += 8192) {
        int i0 = base + tid * 8;
        int v[8], run = 0;
#pragma unroll
        for (int j = 0; j < 8; j++) {
            int vi = (i0 + j < n) ? g_cnt[i0 + j] : 0;
            v[j] = run;
            run += vi;
        }
        int inc = run;
#pragma unroll
        for (int d = 1; d < 32; d <<= 1) {
            int t = __shfl_up_sync(0xffffffffu, inc, d);
            if (lane >= d) inc += t;
        }
        if (lane == 31) wsum[wrp] = inc;
        int carry_in = s_carry;
        __syncthreads();
        if (wrp == 0) {
            int wv = wsum[lane];
            int wi = wv;
#pragma unroll
            for (int d = 1; d < 32; d <<= 1) {
                int t = __shfl_up_sync(0xffffffffu, wi, d);
                if (lane >= d) wi += t;
            }
            wsum[lane] = wi - wv;
            if (lane == 31) s_carry = carry_in + wi;
        }
        __syncthreads();
        int thr_excl = carry_in + wsum[wrp] + (inc - run);
#pragma unroll
        for (int j = 0; j < 8; j++) {
            int i = i0 + j;
            if (i < n) { g_rowptr[i] = thr_excl + v[j]; g_wptr[i] = thr_excl + v[j]; }
        }
        __syncthreads();
    }
    if (tid == 0) g_rowptr[n] = s_carry;
}

__global__ void k_scatter(const int* __restrict__ ei, int E) {
    int e = blockIdx.x * blockDim.x + threadIdx.x;
    int total = E + N_NODES;
    if (e >= total) return;
    int s, d;
    if (e < E) { s = ei[e]; d = ei[E + e]; }
    else       { s = d = e - E; }
    if ((unsigned)d >= (unsigned)N_NODES || (unsigned)s >= (unsigned)N_NODES) return;
    int pos = atomicAdd(&g_wptr[d], 1);
    if ((unsigned)pos < (unsigned)(MAXE + N_NODES)) g_csrsrc[pos] = s;
}

// ---------------------------------------------------------------------------
// Triple-buffered cp.async mma GEMM, 256 threads = 8 warps (4M x 2N),
// two CTAs per SM, ONE barrier per K-chunk.
// AFP32: A staged raw fp32 (seg-swizzled), split to bf16 hi/lo at frag load.
// Row offset rbase allows partial-M launches (grid.y covers a row range).
// ---------------------------------------------------------------------------
template <int NTOT, int NT, int KTOT, bool AFP32>
__device__ __forceinline__ void gemm_mma_body(const float* __restrict__ Af,
                                              const __nv_bfloat16* __restrict__ Ahi,
                                              const __nv_bfloat16* __restrict__ Alo,
                                              const __nv_bfloat16* __restrict__ Bhi,
                                              const __nv_bfloat16* __restrict__ Blo,
                                              float* __restrict__ Cout, int M, int rbase) {
    constexpr int BK  = 32;
    constexpr int NCH = KTOT / BK;
    constexpr int NFW = NT / 16;
    constexpr int AH = 0;
    constexpr int AL = 10240;
    constexpr int BH = AFP32 ? 16384 : 20480;
    constexpr int BL = BH + NT * 80;
    constexpr int STAGE = BH + NT * 160;

    extern __shared__ char sm[];
    const uint32_t smu = smem_u32(sm);

    const int tid  = threadIdx.x;
    const int w    = tid >> 5;
    const int lane = tid & 31;
    const int g    = lane >> 2;
    const int tig  = lane & 3;
    const int wm   = w & 3;
    const int wn   = w >> 2;
    const int bm   = rbase + blockIdx.y * 128;
    const int bn   = blockIdx.x * NT;

    const int a_lr   = lane & 15;
    const int a_seg  = lane >> 4;
    const int b_row  = (lane & 7) + ((lane >> 4) << 3);
    const int b_seg  = (lane >> 3) & 1;
    const int b2_row = lane & 7;
    const int b2_seg = (lane >> 3) & 1;

    float acc[2][NFW][4];
#pragma unroll
    for (int t = 0; t < 2; t++)
#pragma unroll
        for (int f = 0; f < NFW; f++)
#pragma unroll
            for (int q = 0; q < 4; q++) acc[t][f][q] = 0.f;

    auto stage = [&](int c, int b) {
        const int kk = c * BK;
        const int total = 1024 + NT * 8;
        for (int t = tid; t < total; t += 256) {
            if (t < 1024) {
                if (AFP32) {
                    int r = t >> 3, s = t & 7;
                    int gr = bm + r; if (gr >= M) gr = M - 1;
                    const float* src = Af + (size_t)gr * KTOT + kk + s * 4;
                    uint32_t dst = smu + b * STAGE + r * 128 + ((s ^ (r & 7)) << 4);
                    CP_ASYNC16(dst, src);
                } else {
                    int split = t >> 9, idx = t & 511, r = idx >> 2, seg = idx & 3;
                    int gr = bm + r; if (gr >= M) gr = M - 1;
                    const __nv_bfloat16* src = (split ? Alo : Ahi) + (size_t)gr * KTOT + kk + seg * 8;
                    uint32_t dst = smu + b * STAGE + (split ? AL : AH) + r * 80 + seg * 16;
                    CP_ASYNC16(dst, src);
                }
            } else {
                int j = t - 1024;
                int split = (j >= NT * 4);
                int idx = split ? j - NT * 4 : j;
                int r = idx >> 2, seg = idx & 3;
                const __nv_bfloat16* src = (split ? Blo : Bhi) + (size_t)(bn + r) * KTOT + kk + seg * 8;
                uint32_t dst = smu + b * STAGE + (split ? BL : BH) + r * 80 + seg * 16;
                CP_ASYNC16(dst, src);
            }
        }
    };

    auto compute = [&](int b) {
        const uint32_t pb = smu + b * STAGE;
        const char* pc = sm + (size_t)b * STAGE;
#pragma unroll
        for (int ks = 0; ks < 2; ks++) {
            const int kbyte = ks * 32;
            uint32_t ah[2][4], al[2][4];
            if (AFP32) {
#pragma unroll
                for (int mt = 0; mt < 2; mt++) {
#pragma unroll
                    for (int j = 0; j < 4; j++) {
                        int row = wm * 32 + mt * 16 + g + ((j & 1) << 3);
                        int s = (tig >> 1) + ((j >> 1) << 1) + (ks << 2);
                        int h = tig & 1;
                        const float2 f = *(const float2*)(pc + row * 128 + ((s ^ g) << 4) + (h << 3));
                        uint32_t hi_ = cvt_bf16x2(f.y, f.x);
                        float h0 = __uint_as_float(hi_ << 16);
                        float h1 = __uint_as_float(hi_ & 0xffff0000u);
                        uint32_t lo_ = cvt_bf16x2(f.y - h1, f.x - h0);
                        ah[mt][j] = hi_;
                        al[mt][j] = lo_;
                    }
                }
            } else {
#pragma unroll
                for (int t = 0; t < 2; t++) {
                    uint32_t aoff = (uint32_t)(wm * 32 + t * 16 + a_lr) * 80 + kbyte + a_seg * 16;
                    ldsm_x4(ah[t], pb + AH + aoff);
                    ldsm_x4(al[t], pb + AL + aoff);
                }
            }
            uint32_t bhf[NFW * 2], blf[NFW * 2];
#pragma unroll
            for (int f2 = 0; f2 < NFW / 2; f2++) {
                uint32_t boff = (uint32_t)(wn * (NT / 2) + f2 * 16 + b_row) * 80 + kbyte + b_seg * 16;
                ldsm_x4(&bhf[f2 * 4], pb + BH + boff);
                ldsm_x4(&blf[f2 * 4], pb + BL + boff);
            }
            if (NFW & 1) {
                uint32_t boff = (uint32_t)(wn * (NT / 2) + (NFW - 1) * 8 + b2_row) * 80 + kbyte + b2_seg * 16;
                ldsm_x2(&bhf[(NFW - 1) * 2], pb + BH + boff);
                ldsm_x2(&blf[(NFW - 1) * 2], pb + BL + boff);
            }
#pragma unroll
            for (int f = 0; f < NFW; f++) {
#pragma unroll
                for (int t = 0; t < 2; t++) {
                    mma_bf16(acc[t][f], ah[t], &bhf[f * 2]);
                    mma_bf16(acc[t][f], ah[t], &blf[f * 2]);
                    mma_bf16(acc[t][f], al[t], &bhf[f * 2]);
                }
            }
        }
    };

    stage(0, 0);
    CP_COMMIT();
    stage(1, 1);
    CP_COMMIT();
    for (int c = 0; c < NCH; c++) {
        if (c < NCH - 1) { CP_WAIT(1); } else { CP_WAIT(0); }
        __syncthreads();
        if (c + 2 < NCH) {
            stage(c + 2, (c + 2) % 3);
            CP_COMMIT();
        }
        compute(c % 3);
    }

#pragma unroll
    for (int t = 0; t < 2; t++) {
        const int row0 = bm + wm * 32 + t * 16 + g;
        const int row1 = row0 + 8;
#pragma unroll
        for (int f = 0; f < NFW; f++) {
            const int col = bn + wn * (NT / 2) + f * 8 + tig * 2;
            if (row0 < M) {
                float2 v = {acc[t][f][0], acc[t][f][1]};
                *(float2*)(Cout + (size_t)row0 * NTOT + col) = v;
            }
            if (row1 < M) {
                float2 v = {acc[t][f][2], acc[t][f][3]};
                *(float2*)(Cout + (size_t)row1 * NTOT + col) = v;
            }
        }
    }
}

__global__ void __launch_bounds__(256, 2)
k_gemm1_mma(const float* __restrict__ x) {
    gemm_mma_body<HDIM, 128, IN_C, true>(x, nullptr, nullptr, g_w1t_hi, g_w1t_lo, g_h1, N_NODES, 0);
}
__global__ void __launch_bounds__(256, 2)
k_gemm2_mma(int rbase) {
    gemm_mma_body<H2DIM, 80, HDIM, false>(nullptr, g_a1_hi, g_a1_lo, g_w2t_hi, g_w2t_lo, g_h2, N_NODES, rbase);
}

// ---------------------------------------------------------------------------
// Attention: one warp per destination node, online segment-softmax.
// Edge loop processed 4-wide: all gathers issued before consumption (MLP~8);
// softmax updates stay in edge order (numerics identical to scalar loop).
// ---------------------------------------------------------------------------
template <int CTOT, int VPL>
__device__ __forceinline__ void attn_load(const float* __restrict__ h,
                                          int node, int lane, float* xj) {
    if (VPL == 8) {
        const float4* p = (const float4*)(h + (size_t)node * CTOT + lane * 8);
        float4 a = p[0], b = p[1];
        xj[0] = a.x; xj[1] = a.y; xj[2] = a.z; xj[3] = a.w;
        xj[4] = b.x; xj[5] = b.y; xj[6] = b.z; xj[7] = b.w;
    } else {
        const float* jb = h + (size_t)node * CTOT + lane * VPL;
#pragma unroll
        for (int k = 0; k < VPL; k++) xj[k] = jb[k];
    }
}

template <int CTOT, int VPL, bool FINAL>
__device__ __forceinline__ void attn_body(const float* __restrict__ h,
                                          const float* __restrict__ bias,
                                          float* __restrict__ out,
                                          int nbase, int ncount) {
    int gw   = nbase + ((blockIdx.x * blockDim.x + threadIdx.x) >> 5);
    int lane = threadIdx.x & 31;
    if (gw >= nbase + ncount || gw >= N_NODES) return;

    float xi[VPL];
    attn_load<CTOT, VPL>(h, gw, lane, xi);

    float m = -1e30f, s = 0.f;
    float acc[VPL];
#pragma unroll
    for (int k = 0; k < VPL; k++) acc[k] = 0.f;

    auto upd = [&](float d, const float* xj) {
        float a = d > 0.f ? d : 0.2f * d;
        float mn = fmaxf(m, a);
        float corr = __expf(m - mn);
        float wgt = __expf(a - mn);
        s = s * corr + wgt;
#pragma unroll
        for (int k = 0; k < VPL; k++) acc[k] = fmaf(acc[k], corr, wgt * xj[k]);
        m = mn;
    };

    const int e0 = g_rowptr[gw], e1 = g_rowptr[gw + 1];
    int e = e0;
    for (; e + 3 < e1; e += 4) {
        int s0 = g_csrsrc[e], s1 = g_csrsrc[e + 1];
        int s2 = g_csrsrc[e + 2], s3 = g_csrsrc[e + 3];
        float xj0[VPL], xj1[VPL], xj2[VPL], xj3[VPL];
        attn_load<CTOT, VPL>(h, s0, lane, xj0);
        attn_load<CTOT, VPL>(h, s1, lane, xj1);
        attn_load<CTOT, VPL>(h, s2, lane, xj2);
        attn_load<CTOT, VPL>(h, s3, lane, xj3);
        float d0 = 0.f, d1 = 0.f, d2 = 0.f, d3 = 0.f;
#pragma unroll
        for (int k = 0; k < VPL; k++) {
            d0 = fmaf(xi[k], xj0[k], d0);
            d1 = fmaf(xi[k], xj1[k], d1);
            d2 = fmaf(xi[k], xj2[k], d2);
            d3 = fmaf(xi[k], xj3[k], d3);
        }
#pragma unroll
        for (int sh = 1; sh <= 4; sh <<= 1) {
            d0 += __shfl_xor_sync(0xffffffffu, d0, sh);
            d1 += __shfl_xor_sync(0xffffffffu, d1, sh);
            d2 += __shfl_xor_sync(0xffffffffu, d2, sh);
            d3 += __shfl_xor_sync(0xffffffffu, d3, sh);
        }
        upd(d0, xj0); upd(d1, xj1); upd(d2, xj2); upd(d3, xj3);
    }
    for (; e < e1; e++) {
        int s0 = g_csrsrc[e];
        float xj0[VPL];
        attn_load<CTOT, VPL>(h, s0, lane, xj0);
        float d0 = 0.f;
#pragma unroll
        for (int k = 0; k < VPL; k++) d0 = fmaf(xi[k], xj0[k], d0);
        d0 += __shfl_xor_sync(0xffffffffu, d0, 1);
        d0 += __shfl_xor_sync(0xffffffffu, d0, 2);
        d0 += __shfl_xor_sync(0xffffffffu, d0, 4);
        upd(d0, xj0);
    }
    float inv = 1.f / (s + 1e-16f);

    if (!FINAL) {
#pragma unroll
        for (int k = 0; k < VPL; k++) {
            float v = acc[k] * inv + bias[lane * VPL + k];
            v = v > 0.f ? v : expm1f(v);
            size_t idx = (size_t)gw * CTOT + lane * VPL + k;
            __nv_bfloat16 hh = __float2bfloat16(v);
            g_a1_hi[idx] = hh;
            g_a1_lo[idx] = __float2bfloat16(v - __bfloat162float(hh));
        }
    } else {
        float r[VPL];
#pragma unroll
        for (int k = 0; k < VPL; k++) r[k] = acc[k] * inv;
#pragma unroll
        for (int k = 0; k < VPL; k++) r[k] += __shfl_down_sync(0xffffffffu, r[k], 16);
#pragma unroll
        for (int k = 0; k < VPL; k++) r[k] += __shfl_down_sync(0xffffffffu, r[k], 8);
        float v[VPL];
        float mx = -1e30f;
        if (lane < 8) {
#pragma unroll
            for (int k = 0; k < VPL; k++) {
                v[k] = 0.25f * r[k] + bias[lane * VPL + k];
                mx = fmaxf(mx, v[k]);
            }
        }
        mx = fmaxf(mx, __shfl_xor_sync(0xffffffffu, mx, 1));
        mx = fmaxf(mx, __shfl_xor_sync(0xffffffffu, mx, 2));
        mx = fmaxf(mx, __shfl_xor_sync(0xffffffffu, mx, 4));
        float se = 0.f;
        if (lane < 8) {
#pragma unroll
            for (int k = 0; k < VPL; k++) se += __expf(v[k] - mx);
        }
        se += __shfl_xor_sync(0xffffffffu, se, 1);
        se += __shfl_xor_sync(0xffffffffu, se, 2);
        se += __shfl_xor_sync(0xffffffffu, se, 4);
        float lse = logf(se) + mx;
        if (lane < 8) {
#pragma unroll
            for (int k = 0; k < VPL; k++)
                out[(size_t)gw * OUT_C + lane * VPL + k] = v[k] - lse;
        }
    }
}

__global__ void k_attn1(const float* __restrict__ b1, int nbase, int ncount) {
    attn_body<HDIM, 8, false>(g_h1, b1, nullptr, nbase, ncount);
}
__global__ void k_attn2(const float* __restrict__ b2, float* __restrict__ out) {
    attn_body<H2DIM, 5, true>(g_h2, b2, out, 0, N_NODES);
}

// ---------------------------------------------------------------------------
// Launch: CSR forked beside gemm1; attn1/gemm2 pipelined across node halves.
// ---------------------------------------------------------------------------
extern "C" void kernel_launch(void* const* d_in, const int* in_sizes, int n_in,
                              void* d_out, int out_size) {
    const float* x  = (const float*)d_in[0];
    const int*   ei = (const int*)d_in[1];
    const float* W1 = (const float*)d_in[2];
    const float* b1 = (const float*)d_in[3];
    const float* W2 = (const float*)d_in[4];
    const float* b2 = (const float*)d_in[5];
    float* out = (float*)d_out;
    int E = in_sizes[1] / 2;

    const int SMEM1 = 3 * (16384 + 128 * 160);   // 110592 (x2 CTAs/SM)
    const int SMEM2 = 3 * (20480 + 80 * 160);    // 99840  (x2 CTAs/SM)
    cudaFuncSetAttribute(k_gemm1_mma, cudaFuncAttributeMaxDynamicSharedMemorySize, SMEM1);
    cudaFuncSetAttribute(k_gemm2_mma, cudaFuncAttributeMaxDynamicSharedMemorySize, SMEM2);

    static cudaStream_t s_side = nullptr;
    static cudaEvent_t  s_fork = nullptr, s_join = nullptr, s_a1h0 = nullptr,
                        s_a1h1 = nullptr, s_g2 = nullptr;
    if (s_side == nullptr) {
        cudaStreamCreateWithFlags(&s_side, cudaStreamNonBlocking);
        cudaEventCreateWithFlags(&s_fork, cudaEventDisableTiming);
        cudaEventCreateWithFlags(&s_join, cudaEventDisableTiming);
        cudaEventCreateWithFlags(&s_a1h0, cudaEventDisableTiming);
        cudaEventCreateWithFlags(&s_a1h1, cudaEventDisableTiming);
        cudaEventCreateWithFlags(&s_g2, cudaEventDisableTiming);
    }

    // main: weight prep (gemm1 dependency)
    k_prep_w<<<(IN_C * HDIM + HDIM * H2DIM + 255) / 256, 256>>>(W1, W2);

    // fork: CSR build beside gemm1
    cudaEventRecord(s_fork, 0);
    cudaStreamWaitEvent(s_side, s_fork, 0);
    k_init_cnt<<<(N_NODES + 255) / 256, 256, 0, s_side>>>(out, out_size);
    k_hist<<<(E + 255) / 256, 256, 0, s_side>>>(ei, E);
    k_scan<<<1, 1024, 0, s_side>>>(N_NODES);
    k_scatter<<<(E + N_NODES + 255) / 256, 256, 0, s_side>>>(ei, E);
    cudaEventRecord(s_join, s_side);

    // main: gemm1 concurrent with CSR
    k_gemm1_mma<<<dim3(2, MBLK), 256, SMEM1>>>(x);
    cudaStreamWaitEvent(0, s_join, 0);

    // main: attn1 half 0, then signal gemm2 half 0 on side stream
    k_attn1<<<(NSPLIT * 32 + 255) / 256, 256>>>(b1, 0, NSPLIT);
    cudaEventRecord(s_a1h0, 0);
    cudaStreamWaitEvent(s_side, s_a1h0, 0);
    k_gemm2_mma<<<dim3(2, MBLK0), 256, SMEM2, s_side>>>(0);

    // main: attn1 half 1, then gemm2 half 1 on side stream
    k_attn1<<<((N_NODES - NSPLIT) * 32 + 255) / 256, 256>>>(b1, NSPLIT, N_NODES - NSPLIT);
    cudaEventRecord(s_a1h1, 0);
    cudaStreamWaitEvent(s_side, s_a1h1, 0);
    k_gemm2_mma<<<dim3(2, MBLK - MBLK0), 256, SMEM2, s_side>>>(NSPLIT);
    cudaEventRecord(s_g2, s_side);

    // join: attn2 needs all of gemm2
    cudaStreamWaitEvent(0, s_g2, 0);
    k_attn2<<<(N_NODES * 32 + 255) / 256, 256>>>(b2, out);
}

// round 15
// speedup vs baseline: 1.0402x; 1.0402x over previous
#include <cuda_runtime.h>
#include <cuda_bf16.h>
#include <math.h>
#include <stdint.h>

// Problem constants
#define N_NODES 50000
#define IN_C    512
#define HDIM    256   // H*HID
#define H2DIM   160   // H*OUT_C
#define OUT_C   40
#define MAXE    400000
#define MBLK    391   // ceil(50000/128)

// ---------------------------------------------------------------------------
// Scratch (static device globals)
// ---------------------------------------------------------------------------
__device__ float g_h1[(size_t)N_NODES * HDIM];
__device__ float g_h2[(size_t)N_NODES * H2DIM];
__device__ __align__(16) __nv_bfloat16 g_a1_hi[(size_t)N_NODES * HDIM];
__device__ __align__(16) __nv_bfloat16 g_a1_lo[(size_t)N_NODES * HDIM];
__device__ __align__(16) __nv_bfloat16 g_w1t_hi[(size_t)HDIM * IN_C];   // [n][k]
__device__ __align__(16) __nv_bfloat16 g_w1t_lo[(size_t)HDIM * IN_C];
__device__ __align__(16) __nv_bfloat16 g_w2t_hi[(size_t)H2DIM * HDIM];  // [n][k]
__device__ __align__(16) __nv_bfloat16 g_w2t_lo[(size_t)H2DIM * HDIM];
__device__ int g_cnt[N_NODES];
__device__ int g_rowptr[N_NODES + 1];
__device__ int g_wptr[N_NODES];
__device__ int g_csrsrc[MAXE + N_NODES];

// ---------------------------------------------------------------------------
// mma.sync bf16 + ldmatrix + cp.async helpers (family-common ISA)
// ---------------------------------------------------------------------------
__device__ __forceinline__ void mma_bf16(float* d, const uint32_t* a, const uint32_t* b) {
    asm volatile(
        "mma.sync.aligned.m16n8k16.row.col.f32.bf16.bf16.f32 "
        "{%0,%1,%2,%3}, {%4,%5,%6,%7}, {%8,%9}, {%0,%1,%2,%3};"
        : "+f"(d[0]), "+f"(d[1]), "+f"(d[2]), "+f"(d[3])
        : "r"(a[0]), "r"(a[1]), "r"(a[2]), "r"(a[3]), "r"(b[0]), "r"(b[1]));
}
__device__ __forceinline__ void ldsm_x4(uint32_t* r, uint32_t addr) {
    asm volatile("ldmatrix.sync.aligned.m8n8.x4.shared.b16 {%0,%1,%2,%3}, [%4];"
        : "=r"(r[0]), "=r"(r[1]), "=r"(r[2]), "=r"(r[3]) : "r"(addr));
}
__device__ __forceinline__ void ldsm_x2(uint32_t* r, uint32_t addr) {
    asm volatile("ldmatrix.sync.aligned.m8n8.x2.shared.b16 {%0,%1}, [%2];"
        : "=r"(r[0]), "=r"(r[1]) : "r"(addr));
}
__device__ __forceinline__ uint32_t smem_u32(const void* p) {
    uint32_t a;
    asm("{ .reg .u64 t; cvta.to.shared.u64 t, %1; cvt.u32.u64 %0, t; }" : "=r"(a) : "l"(p));
    return a;
}
#define CP_ASYNC16(dst, src) \
    asm volatile("cp.async.cg.shared.global [%0], [%1], 16;" :: "r"(dst), "l"(src))
#define CP_COMMIT()  asm volatile("cp.async.commit_group;" ::: "memory")
#define CP_WAIT(n)   asm volatile("cp.async.wait_group %0;" :: "n"(n) : "memory")

__device__ __forceinline__ uint32_t cvt_bf16x2(float hi_elem, float lo_elem) {
    uint32_t r;
    asm("cvt.rn.bf16x2.f32 %0, %1, %2;" : "=r"(r) : "f"(hi_elem), "f"(lo_elem));
    return r;
}

// ---------------------------------------------------------------------------
// Fused weight prep: transpose + bf16 split for W1 and W2 in one launch.
// ---------------------------------------------------------------------------
__global__ void k_prep_w(const float* __restrict__ W1, const float* __restrict__ W2) {
    int idx = blockIdx.x * blockDim.x + threadIdx.x;
    const int N1 = IN_C * HDIM;
    if (idx < N1) {
        int k = idx / HDIM, n = idx % HDIM;
        float v = W1[idx];
        __nv_bfloat16 h = __float2bfloat16(v);
        g_w1t_hi[(size_t)n * IN_C + k] = h;
        g_w1t_lo[(size_t)n * IN_C + k] = __float2bfloat16(v - __bfloat162float(h));
    } else if (idx < N1 + HDIM * H2DIM) {
        int j = idx - N1;
        int k = j / H2DIM, n = j % H2DIM;
        float v = W2[j];
        __nv_bfloat16 h = __float2bfloat16(v);
        g_w2t_hi[(size_t)n * HDIM + k] = h;
        g_w2t_lo[(size_t)n * HDIM + k] = __float2bfloat16(v - __bfloat162float(h));
    }
}

// ---------------------------------------------------------------------------
// CSR construction (+ output tail zeroing folded into init)
// ---------------------------------------------------------------------------
__global__ void k_init_cnt(float* out, int out_size) {
    int i = blockIdx.x * blockDim.x + threadIdx.x;
    if (i < N_NODES) g_cnt[i] = 1;
    if (blockIdx.x == 0) {
        for (int j = N_NODES * OUT_C + threadIdx.x; j < out_size; j += blockDim.x)
            out[j] = 0.f;
    }
}
__global__ void k_hist(const int* __restrict__ ei, int E) {
    int e = blockIdx.x * blockDim.x + threadIdx.x;
    if (e < E) {
        int d = ei[E + e];
        if ((unsigned)d < (unsigned)N_NODES) atomicAdd(&g_cnt[d], 1);
    }
}

__global__ void k_scan(int n) {
    __shared__ int wsum[32];
    __shared__ int s_carry;
    const int tid = threadIdx.x;
    const int lane = tid & 31, wrp = tid >> 5;
    if (tid == 0) s_carry = 0;
    __syncthreads();
    for (int base = 0; base < n; base += 8192) {
        int i0 = base + tid * 8;
        int v[8], run = 0;
#pragma unroll
        for (int j = 0; j < 8; j++) {
            int vi = (i0 + j < n) ? g_cnt[i0 + j] : 0;
            v[j] = run;
            run += vi;
        }
        int inc = run;
#pragma unroll
        for (int d = 1; d < 32; d <<= 1) {
            int t = __shfl_up_sync(0xffffffffu, inc, d);
            if (lane >= d) inc += t;
        }
        if (lane == 31) wsum[wrp] = inc;
        int carry_in = s_carry;
        __syncthreads();
        if (wrp == 0) {
            int wv = wsum[lane];
            int wi = wv;
#pragma unroll
            for (int d = 1; d < 32; d <<= 1) {
                int t = __shfl_up_sync(0xffffffffu, wi, d);
                if (lane >= d) wi += t;
            }
            wsum[lane] = wi - wv;
            if (lane == 31) s_carry = carry_in + wi;
        }
        __syncthreads();
        int thr_excl = carry_in + wsum[wrp] + (inc - run);
#pragma unroll
        for (int j = 0; j < 8; j++) {
            int i = i0 + j;
            if (i < n) { g_rowptr[i] = thr_excl + v[j]; g_wptr[i] = thr_excl + v[j]; }
        }
        __syncthreads();
    }
    if (tid == 0) g_rowptr[n] = s_carry;
}

__global__ void k_scatter(const int* __restrict__ ei, int E) {
    int e = blockIdx.x * blockDim.x + threadIdx.x;
    int total = E + N_NODES;
    if (e >= total) return;
    int s, d;
    if (e < E) { s = ei[e]; d = ei[E + e]; }
    else       { s = d = e - E; }
    if ((unsigned)d >= (unsigned)N_NODES || (unsigned)s >= (unsigned)N_NODES) return;
    int pos = atomicAdd(&g_wptr[d], 1);
    if ((unsigned)pos < (unsigned)(MAXE + N_NODES)) g_csrsrc[pos] = s;
}

// ---------------------------------------------------------------------------
// Triple-buffered cp.async mma GEMM, 256 threads = 8 warps (4M x 2N),
// two CTAs per SM, ONE barrier per K-chunk.
// AFP32: A staged raw fp32 (seg-swizzled), split to bf16 hi/lo at frag load.
// ---------------------------------------------------------------------------
template <int NTOT, int NT, int KTOT, bool AFP32>
__device__ __forceinline__ void gemm_mma_body(const float* __restrict__ Af,
                                              const __nv_bfloat16* __restrict__ Ahi,
                                              const __nv_bfloat16* __restrict__ Alo,
                                              const __nv_bfloat16* __restrict__ Bhi,
                                              const __nv_bfloat16* __restrict__ Blo,
                                              float* __restrict__ Cout, int M) {
    constexpr int BK  = 32;
    constexpr int NCH = KTOT / BK;
    constexpr int NFW = NT / 16;
    constexpr int AH = 0;
    constexpr int AL = 10240;
    constexpr int BH = AFP32 ? 16384 : 20480;
    constexpr int BL = BH + NT * 80;
    constexpr int STAGE = BH + NT * 160;

    extern __shared__ char sm[];
    const uint32_t smu = smem_u32(sm);

    const int tid  = threadIdx.x;
    const int w    = tid >> 5;
    const int lane = tid & 31;
    const int g    = lane >> 2;
    const int tig  = lane & 3;
    const int wm   = w & 3;
    const int wn   = w >> 2;
    const int bm   = blockIdx.y * 128;
    const int bn   = blockIdx.x * NT;

    const int a_lr   = lane & 15;
    const int a_seg  = lane >> 4;
    const int b_row  = (lane & 7) + ((lane >> 4) << 3);
    const int b_seg  = (lane >> 3) & 1;
    const int b2_row = lane & 7;
    const int b2_seg = (lane >> 3) & 1;

    float acc[2][NFW][4];
#pragma unroll
    for (int t = 0; t < 2; t++)
#pragma unroll
        for (int f = 0; f < NFW; f++)
#pragma unroll
            for (int q = 0; q < 4; q++) acc[t][f][q] = 0.f;

    auto stage = [&](int c, int b) {
        const int kk = c * BK;
        const int total = 1024 + NT * 8;
        for (int t = tid; t < total; t += 256) {
            if (t < 1024) {
                if (AFP32) {
                    int r = t >> 3, s = t & 7;
                    int gr = bm + r; if (gr >= M) gr = M - 1;
                    const float* src = Af + (size_t)gr * KTOT + kk + s * 4;
                    uint32_t dst = smu + b * STAGE + r * 128 + ((s ^ (r & 7)) << 4);
                    CP_ASYNC16(dst, src);
                } else {
                    int split = t >> 9, idx = t & 511, r = idx >> 2, seg = idx & 3;
                    int gr = bm + r; if (gr >= M) gr = M - 1;
                    const __nv_bfloat16* src = (split ? Alo : Ahi) + (size_t)gr * KTOT + kk + seg * 8;
                    uint32_t dst = smu + b * STAGE + (split ? AL : AH) + r * 80 + seg * 16;
                    CP_ASYNC16(dst, src);
                }
            } else {
                int j = t - 1024;
                int split = (j >= NT * 4);
                int idx = split ? j - NT * 4 : j;
                int r = idx >> 2, seg = idx & 3;
                const __nv_bfloat16* src = (split ? Blo : Bhi) + (size_t)(bn + r) * KTOT + kk + seg * 8;
                uint32_t dst = smu + b * STAGE + (split ? BL : BH) + r * 80 + seg * 16;
                CP_ASYNC16(dst, src);
            }
        }
    };

    auto compute = [&](int b) {
        const uint32_t pb = smu + b * STAGE;
        const char* pc = sm + (size_t)b * STAGE;
#pragma unroll
        for (int ks = 0; ks < 2; ks++) {
            const int kbyte = ks * 32;
            uint32_t ah[2][4], al[2][4];
            if (AFP32) {
#pragma unroll
                for (int mt = 0; mt < 2; mt++) {
#pragma unroll
                    for (int j = 0; j < 4; j++) {
                        int row = wm * 32 + mt * 16 + g + ((j & 1) << 3);
                        int s = (tig >> 1) + ((j >> 1) << 1) + (ks << 2);
                        int h = tig & 1;
                        const float2 f = *(const float2*)(pc + row * 128 + ((s ^ g) << 4) + (h << 3));
                        uint32_t hi_ = cvt_bf16x2(f.y, f.x);
                        float h0 = __uint_as_float(hi_ << 16);
                        float h1 = __uint_as_float(hi_ & 0xffff0000u);
                        uint32_t lo_ = cvt_bf16x2(f.y - h1, f.x - h0);
                        ah[mt][j] = hi_;
                        al[mt][j] = lo_;
                    }
                }
            } else {
#pragma unroll
                for (int t = 0; t < 2; t++) {
                    uint32_t aoff = (uint32_t)(wm * 32 + t * 16 + a_lr) * 80 + kbyte + a_seg * 16;
                    ldsm_x4(ah[t], pb + AH + aoff);
                    ldsm_x4(al[t], pb + AL + aoff);
                }
            }
            uint32_t bhf[NFW * 2], blf[NFW * 2];
#pragma unroll
            for (int f2 = 0; f2 < NFW / 2; f2++) {
                uint32_t boff = (uint32_t)(wn * (NT / 2) + f2 * 16 + b_row) * 80 + kbyte + b_seg * 16;
                ldsm_x4(&bhf[f2 * 4], pb + BH + boff);
                ldsm_x4(&blf[f2 * 4], pb + BL + boff);
            }
            if (NFW & 1) {
                uint32_t boff = (uint32_t)(wn * (NT / 2) + (NFW - 1) * 8 + b2_row) * 80 + kbyte + b2_seg * 16;
                ldsm_x2(&bhf[(NFW - 1) * 2], pb + BH + boff);
                ldsm_x2(&blf[(NFW - 1) * 2], pb + BL + boff);
            }
#pragma unroll
            for (int f = 0; f < NFW; f++) {
#pragma unroll
                for (int t = 0; t < 2; t++) {
                    mma_bf16(acc[t][f], ah[t], &bhf[f * 2]);
                    mma_bf16(acc[t][f], ah[t], &blf[f * 2]);
                    mma_bf16(acc[t][f], al[t], &bhf[f * 2]);
                }
            }
        }
    };

    stage(0, 0);
    CP_COMMIT();
    stage(1, 1);
    CP_COMMIT();
    for (int c = 0; c < NCH; c++) {
        if (c < NCH - 1) { CP_WAIT(1); } else { CP_WAIT(0); }
        __syncthreads();
        if (c + 2 < NCH) {
            stage(c + 2, (c + 2) % 3);
            CP_COMMIT();
        }
        compute(c % 3);
    }

#pragma unroll
    for (int t = 0; t < 2; t++) {
        const int row0 = bm + wm * 32 + t * 16 + g;
        const int row1 = row0 + 8;
#pragma unroll
        for (int f = 0; f < NFW; f++) {
            const int col = bn + wn * (NT / 2) + f * 8 + tig * 2;
            if (row0 < M) {
                float2 v = {acc[t][f][0], acc[t][f][1]};
                *(float2*)(Cout + (size_t)row0 * NTOT + col) = v;
            }
            if (row1 < M) {
                float2 v = {acc[t][f][2], acc[t][f][3]};
                *(float2*)(Cout + (size_t)row1 * NTOT + col) = v;
            }
        }
    }
}

__global__ void __launch_bounds__(256, 2)
k_gemm1_mma(const float* __restrict__ x) {
    gemm_mma_body<HDIM, 128, IN_C, true>(x, nullptr, nullptr, g_w1t_hi, g_w1t_lo, g_h1, N_NODES);
}
__global__ void __launch_bounds__(256, 2)
k_gemm2_mma() {
    gemm_mma_body<H2DIM, 80, HDIM, false>(nullptr, g_a1_hi, g_a1_lo, g_w2t_hi, g_w2t_lo, g_h2, N_NODES);
}

// ---------------------------------------------------------------------------
// Attention: one warp per destination node, online segment-softmax.
// Edge loop processed 4-wide: all gathers issued before consumption (MLP~8);
// softmax updates stay in edge order (numerics identical to scalar loop).
// ---------------------------------------------------------------------------
template <int CTOT, int VPL>
__device__ __forceinline__ void attn_load(const float* __restrict__ h,
                                          int node, int lane, float* xj) {
    if (VPL == 8) {
        const float4* p = (const float4*)(h + (size_t)node * CTOT + lane * 8);
        float4 a = p[0], b = p[1];
        xj[0] = a.x; xj[1] = a.y; xj[2] = a.z; xj[3] = a.w;
        xj[4] = b.x; xj[5] = b.y; xj[6] = b.z; xj[7] = b.w;
    } else {
        const float* jb = h + (size_t)node * CTOT + lane * VPL;
#pragma unroll
        for (int k = 0; k < VPL; k++) xj[k] = jb[k];
    }
}

template <int CTOT, int VPL, bool FINAL>
__device__ __forceinline__ void attn_body(const float* __restrict__ h,
                                          const float* __restrict__ bias,
                                          float* __restrict__ out) {
    int gw   = (blockIdx.x * blockDim.x + threadIdx.x) >> 5;
    int lane = threadIdx.x & 31;
    if (gw >= N_NODES) return;

    float xi[VPL];
    attn_load<CTOT, VPL>(h, gw, lane, xi);

    float m = -1e30f, s = 0.f;
    float acc[VPL];
#pragma unroll
    for (int k = 0; k < VPL; k++) acc[k] = 0.f;

    auto upd = [&](float d, const float* xj) {
        float a = d > 0.f ? d : 0.2f * d;
        float mn = fmaxf(m, a);
        float corr = __expf(m - mn);
        float wgt = __expf(a - mn);
        s = s * corr + wgt;
#pragma unroll
        for (int k = 0; k < VPL; k++) acc[k] = fmaf(acc[k], corr, wgt * xj[k]);
        m = mn;
    };

    const int e0 = g_rowptr[gw], e1 = g_rowptr[gw + 1];
    int e = e0;
    for (; e + 3 < e1; e += 4) {
        int s0 = g_csrsrc[e], s1 = g_csrsrc[e + 1];
        int s2 = g_csrsrc[e + 2], s3 = g_csrsrc[e + 3];
        float xj0[VPL], xj1[VPL], xj2[VPL], xj3[VPL];
        attn_load<CTOT, VPL>(h, s0, lane, xj0);
        attn_load<CTOT, VPL>(h, s1, lane, xj1);
        attn_load<CTOT, VPL>(h, s2, lane, xj2);
        attn_load<CTOT, VPL>(h, s3, lane, xj3);
        float d0 = 0.f, d1 = 0.f, d2 = 0.f, d3 = 0.f;
#pragma unroll
        for (int k = 0; k < VPL; k++) {
            d0 = fmaf(xi[k], xj0[k], d0);
            d1 = fmaf(xi[k], xj1[k], d1);
            d2 = fmaf(xi[k], xj2[k], d2);
            d3 = fmaf(xi[k], xj3[k], d3);
        }
#pragma unroll
        for (int sh = 1; sh <= 4; sh <<= 1) {
            d0 += __shfl_xor_sync(0xffffffffu, d0, sh);
            d1 += __shfl_xor_sync(0xffffffffu, d1, sh);
            d2 += __shfl_xor_sync(0xffffffffu, d2, sh);
            d3 += __shfl_xor_sync(0xffffffffu, d3, sh);
        }
        upd(d0, xj0); upd(d1, xj1); upd(d2, xj2); upd(d3, xj3);
    }
    for (; e < e1; e++) {
        int s0 = g_csrsrc[e];
        float xj0[VPL];
        attn_load<CTOT, VPL>(h, s0, lane, xj0);
        float d0 = 0.f;
#pragma unroll
        for (int k = 0; k < VPL; k++) d0 = fmaf(xi[k], xj0[k], d0);
        d0 += __shfl_xor_sync(0xffffffffu, d0, 1);
        d0 += __shfl_xor_sync(0xffffffffu, d0, 2);
        d0 += __shfl_xor_sync(0xffffffffu, d0, 4);
        upd(d0, xj0);
    }
    float inv = 1.f / (s + 1e-16f);

    if (!FINAL) {
#pragma unroll
        for (int k = 0; k < VPL; k++) {
            float v = acc[k] * inv + bias[lane * VPL + k];
            v = v > 0.f ? v : expm1f(v);
            size_t idx = (size_t)gw * CTOT + lane * VPL + k;
            __nv_bfloat16 hh = __float2bfloat16(v);
            g_a1_hi[idx] = hh;
            g_a1_lo[idx] = __float2bfloat16(v - __bfloat162float(hh));
        }
    } else {
        float r[VPL];
#pragma unroll
        for (int k = 0; k < VPL; k++) r[k] = acc[k] * inv;
#pragma unroll
        for (int k = 0; k < VPL; k++) r[k] += __shfl_down_sync(0xffffffffu, r[k], 16);
#pragma unroll
        for (int k = 0; k < VPL; k++) r[k] += __shfl_down_sync(0xffffffffu, r[k], 8);
        float v[VPL];
        float mx = -1e30f;
        if (lane < 8) {
#pragma unroll
            for (int k = 0; k < VPL; k++) {
                v[k] = 0.25f * r[k] + bias[lane * VPL + k];
                mx = fmaxf(mx, v[k]);
            }
        }
        mx = fmaxf(mx, __shfl_xor_sync(0xffffffffu, mx, 1));
        mx = fmaxf(mx, __shfl_xor_sync(0xffffffffu, mx, 2));
        mx = fmaxf(mx, __shfl_xor_sync(0xffffffffu, mx, 4));
        float se = 0.f;
        if (lane < 8) {
#pragma unroll
            for (int k = 0; k < VPL; k++) se += __expf(v[k] - mx);
        }
        se += __shfl_xor_sync(0xffffffffu, se, 1);
        se += __shfl_xor_sync(0xffffffffu, se, 2);
        se += __shfl_xor_sync(0xffffffffu, se, 4);
        float lse = logf(se) + mx;
        if (lane < 8) {
#pragma unroll
            for (int k = 0; k < VPL; k++)
                out[(size_t)gw * OUT_C + lane * VPL + k] = v[k] - lse;
        }
    }
}

__global__ void k_attn1(const float* __restrict__ b1) {
    attn_body<HDIM, 8, false>(g_h1, b1, nullptr);
}
__global__ void k_attn2(const float* __restrict__ b2, float* __restrict__ out) {
    attn_body<H2DIM, 5, true>(g_h2, b2, out);
}

// ---------------------------------------------------------------------------
// Launch: CSR build forked onto a side stream, overlapping gemm1 (R13 layout).
// ---------------------------------------------------------------------------
extern "C" void kernel_launch(void* const* d_in, const int* in_sizes, int n_in,
                              void* d_out, int out_size) {
    const float* x  = (const float*)d_in[0];
    const int*   ei = (const int*)d_in[1];
    const float* W1 = (const float*)d_in[2];
    const float* b1 = (const float*)d_in[3];
    const float* W2 = (const float*)d_in[4];
    const float* b2 = (const float*)d_in[5];
    float* out = (float*)d_out;
    int E = in_sizes[1] / 2;

    const int SMEM1 = 3 * (16384 + 128 * 160);   // 110592 (x2 CTAs/SM)
    const int SMEM2 = 3 * (20480 + 80 * 160);    // 99840  (x2 CTAs/SM)
    cudaFuncSetAttribute(k_gemm1_mma, cudaFuncAttributeMaxDynamicSharedMemorySize, SMEM1);
    cudaFuncSetAttribute(k_gemm2_mma, cudaFuncAttributeMaxDynamicSharedMemorySize, SMEM2);

    static cudaStream_t s_side = nullptr;
    static cudaEvent_t  s_fork = nullptr, s_join = nullptr;
    if (s_side == nullptr) {
        cudaStreamCreateWithFlags(&s_side, cudaStreamNonBlocking);
        cudaEventCreateWithFlags(&s_fork, cudaEventDisableTiming);
        cudaEventCreateWithFlags(&s_join, cudaEventDisableTiming);
    }

    // main: weight prep (gemm1 dependency)
    k_prep_w<<<(IN_C * HDIM + HDIM * H2DIM + 255) / 256, 256>>>(W1, W2);

    // fork: CSR build beside gemm1
    cudaEventRecord(s_fork, 0);
    cudaStreamWaitEvent(s_side, s_fork, 0);
    k_init_cnt<<<(N_NODES + 255) / 256, 256, 0, s_side>>>(out, out_size);
    k_hist<<<(E + 255) / 256, 256, 0, s_side>>>(ei, E);
    k_scan<<<1, 1024, 0, s_side>>>(N_NODES);
    k_scatter<<<(E + N_NODES + 255) / 256, 256, 0, s_side>>>(ei, E);
    cudaEventRecord(s_join, s_side);

    // main: gemm1 concurrent with CSR
    k_gemm1_mma<<<dim3(2, MBLK), 256, SMEM1>>>(x);

    // join: attn1 needs both gemm1 (main) and CSR (side)
    cudaStreamWaitEvent(0, s_join, 0);
    k_attn1<<<(N_NODES + 7) / 8, 256>>>(b1);
    k_gemm2_mma<<<dim3(2, MBLK), 256, SMEM2>>>();
    k_attn2<<<(N_NODES + 7) / 8, 256>>>(b2, out);
}

// round 16
// speedup vs baseline: 1.0758x; 1.0342x over previous
#include <cuda_runtime.h>
#include <cuda_bf16.h>
#include <math.h>
#include <stdint.h>

// Problem constants
#define N_NODES 50000
#define IN_C    512
#define HDIM    256   // H*HID
#define H2DIM   160   // H*OUT_C
#define OUT_C   40
#define MAXE    400000
#define MBLK    391   // ceil(50000/128)

// ---------------------------------------------------------------------------
// Scratch (static device globals)
// ---------------------------------------------------------------------------
__device__ float g_h1[(size_t)N_NODES * HDIM];
__device__ float g_h2[(size_t)N_NODES * H2DIM];
__device__ __align__(16) __nv_bfloat16 g_a1_hi[(size_t)N_NODES * HDIM];
__device__ __align__(16) __nv_bfloat16 g_a1_lo[(size_t)N_NODES * HDIM];
__device__ __align__(16) __nv_bfloat16 g_w1t_hi[(size_t)HDIM * IN_C];   // [n][k]
__device__ __align__(16) __nv_bfloat16 g_w1t_lo[(size_t)HDIM * IN_C];
__device__ __align__(16) __nv_bfloat16 g_w2t_hi[(size_t)H2DIM * HDIM];  // [n][k]
__device__ __align__(16) __nv_bfloat16 g_w2t_lo[(size_t)H2DIM * HDIM];
__device__ int g_cnt[N_NODES];
__device__ int g_rowptr[N_NODES + 1];
__device__ int g_wptr[N_NODES];
__device__ int g_csrsrc[MAXE + N_NODES];

// ---------------------------------------------------------------------------
// mma.sync bf16 + ldmatrix + cp.async helpers (family-common ISA)
// ---------------------------------------------------------------------------
__device__ __forceinline__ void mma_bf16(float* d, const uint32_t* a, const uint32_t* b) {
    asm volatile(
        "mma.sync.aligned.m16n8k16.row.col.f32.bf16.bf16.f32 "
        "{%0,%1,%2,%3}, {%4,%5,%6,%7}, {%8,%9}, {%0,%1,%2,%3};"
        : "+f"(d[0]), "+f"(d[1]), "+f"(d[2]), "+f"(d[3])
        : "r"(a[0]), "r"(a[1]), "r"(a[2]), "r"(a[3]), "r"(b[0]), "r"(b[1]));
}
__device__ __forceinline__ void ldsm_x4(uint32_t* r, uint32_t addr) {
    asm volatile("ldmatrix.sync.aligned.m8n8.x4.shared.b16 {%0,%1,%2,%3}, [%4];"
        : "=r"(r[0]), "=r"(r[1]), "=r"(r[2]), "=r"(r[3]) : "r"(addr));
}
__device__ __forceinline__ void ldsm_x2(uint32_t* r, uint32_t addr) {
    asm volatile("ldmatrix.sync.aligned.m8n8.x2.shared.b16 {%0,%1}, [%2];"
        : "=r"(r[0]), "=r"(r[1]) : "r"(addr));
}
__device__ __forceinline__ uint32_t smem_u32(const void* p) {
    uint32_t a;
    asm("{ .reg .u64 t; cvta.to.shared.u64 t, %1; cvt.u32.u64 %0, t; }" : "=r"(a) : "l"(p));
    return a;
}
#define CP_ASYNC16(dst, src) \
    asm volatile("cp.async.cg.shared.global [%0], [%1], 16;" :: "r"(dst), "l"(src))
#define CP_COMMIT()  asm volatile("cp.async.commit_group;" ::: "memory")
#define CP_WAIT(n)   asm volatile("cp.async.wait_group %0;" :: "n"(n) : "memory")

__device__ __forceinline__ uint32_t cvt_bf16x2(float hi_elem, float lo_elem) {
    uint32_t r;
    asm("cvt.rn.bf16x2.f32 %0, %1, %2;" : "=r"(r) : "f"(hi_elem), "f"(lo_elem));
    return r;
}

// ---------------------------------------------------------------------------
// Fused weight prep: transpose + bf16 split for W1 and W2 in one launch.
// ---------------------------------------------------------------------------
__global__ void k_prep_w(const float* __restrict__ W1, const float* __restrict__ W2) {
    int idx = blockIdx.x * blockDim.x + threadIdx.x;
    const int N1 = IN_C * HDIM;
    if (idx < N1) {
        int k = idx / HDIM, n = idx % HDIM;
        float v = W1[idx];
        __nv_bfloat16 h = __float2bfloat16(v);
        g_w1t_hi[(size_t)n * IN_C + k] = h;
        g_w1t_lo[(size_t)n * IN_C + k] = __float2bfloat16(v - __bfloat162float(h));
    } else if (idx < N1 + HDIM * H2DIM) {
        int j = idx - N1;
        int k = j / H2DIM, n = j % H2DIM;
        float v = W2[j];
        __nv_bfloat16 h = __float2bfloat16(v);
        g_w2t_hi[(size_t)n * HDIM + k] = h;
        g_w2t_lo[(size_t)n * HDIM + k] = __float2bfloat16(v - __bfloat162float(h));
    }
}

// ---------------------------------------------------------------------------
// CSR construction (+ output tail zeroing folded into init)
// ---------------------------------------------------------------------------
__global__ void k_init_cnt(float* out, int out_size) {
    int i = blockIdx.x * blockDim.x + threadIdx.x;
    if (i < N_NODES) g_cnt[i] = 1;
    if (blockIdx.x == 0) {
        for (int j = N_NODES * OUT_C + threadIdx.x; j < out_size; j += blockDim.x)
            out[j] = 0.f;
    }
}
__global__ void k_hist(const int* __restrict__ ei, int E) {
    int e = blockIdx.x * blockDim.x + threadIdx.x;
    if (e < E) {
        int d = ei[E + e];
        if ((unsigned)d < (unsigned)N_NODES) atomicAdd(&g_cnt[d], 1);
    }
}

__global__ void k_scan(int n) {
    __shared__ int wsum[32];
    __shared__ int s_carry;
    const int tid = threadIdx.x;
    const int lane = tid & 31, wrp = tid >> 5;
    if (tid == 0) s_carry = 0;
    __syncthreads();
    for (int base = 0; base < n; base += 8192) {
        int i0 = base + tid * 8;
        int v[8], run = 0;
#pragma unroll
        for (int j = 0; j < 8; j++) {
            int vi = (i0 + j < n) ? g_cnt[i0 + j] : 0;
            v[j] = run;
            run += vi;
        }
        int inc = run;
#pragma unroll
        for (int d = 1; d < 32; d <<= 1) {
            int t = __shfl_up_sync(0xffffffffu, inc, d);
            if (lane >= d) inc += t;
        }
        if (lane == 31) wsum[wrp] = inc;
        int carry_in = s_carry;
        __syncthreads();
        if (wrp == 0) {
            int wv = wsum[lane];
            int wi = wv;
#pragma unroll
            for (int d = 1; d < 32; d <<= 1) {
                int t = __shfl_up_sync(0xffffffffu, wi, d);
                if (lane >= d) wi += t;
            }
            wsum[lane] = wi - wv;
            if (lane == 31) s_carry = carry_in + wi;
        }
        __syncthreads();
        int thr_excl = carry_in + wsum[wrp] + (inc - run);
#pragma unroll
        for (int j = 0; j < 8; j++) {
            int i = i0 + j;
            if (i < n) { g_rowptr[i] = thr_excl + v[j]; g_wptr[i] = thr_excl + v[j]; }
        }
        __syncthreads();
    }
    if (tid == 0) g_rowptr[n] = s_carry;
}

__global__ void k_scatter(const int* __restrict__ ei, int E) {
    int e = blockIdx.x * blockDim.x + threadIdx.x;
    int total = E + N_NODES;
    if (e >= total) return;
    int s, d;
    if (e < E) { s = ei[e]; d = ei[E + e]; }
    else       { s = d = e - E; }
    if ((unsigned)d >= (unsigned)N_NODES || (unsigned)s >= (unsigned)N_NODES) return;
    int pos = atomicAdd(&g_wptr[d], 1);
    if ((unsigned)pos < (unsigned)(MAXE + N_NODES)) g_csrsrc[pos] = s;
}

// ---------------------------------------------------------------------------
// Triple-buffered cp.async mma GEMM, 256 threads = 8 warps (4M x 2N),
// two CTAs per SM, ONE barrier per K-chunk.
// AFP32: A staged raw fp32 (seg-swizzled), split to bf16 hi/lo at frag load.
// ---------------------------------------------------------------------------
template <int NTOT, int NT, int KTOT, bool AFP32>
__device__ __forceinline__ void gemm_mma_body(const float* __restrict__ Af,
                                              const __nv_bfloat16* __restrict__ Ahi,
                                              const __nv_bfloat16* __restrict__ Alo,
                                              const __nv_bfloat16* __restrict__ Bhi,
                                              const __nv_bfloat16* __restrict__ Blo,
                                              float* __restrict__ Cout, int M) {
    constexpr int BK  = 32;
    constexpr int NCH = KTOT / BK;
    constexpr int NFW = NT / 16;
    constexpr int AH = 0;
    constexpr int AL = 10240;
    constexpr int BH = AFP32 ? 16384 : 20480;
    constexpr int BL = BH + NT * 80;
    constexpr int STAGE = BH + NT * 160;

    extern __shared__ char sm[];
    const uint32_t smu = smem_u32(sm);

    const int tid  = threadIdx.x;
    const int w    = tid >> 5;
    const int lane = tid & 31;
    const int g    = lane >> 2;
    const int tig  = lane & 3;
    const int wm   = w & 3;
    const int wn   = w >> 2;
    const int bm   = blockIdx.y * 128;
    const int bn   = blockIdx.x * NT;

    const int a_lr   = lane & 15;
    const int a_seg  = lane >> 4;
    const int b_row  = (lane & 7) + ((lane >> 4) << 3);
    const int b_seg  = (lane >> 3) & 1;
    const int b2_row = lane & 7;
    const int b2_seg = (lane >> 3) & 1;

    float acc[2][NFW][4];
#pragma unroll
    for (int t = 0; t < 2; t++)
#pragma unroll
        for (int f = 0; f < NFW; f++)
#pragma unroll
            for (int q = 0; q < 4; q++) acc[t][f][q] = 0.f;

    auto stage = [&](int c, int b) {
        const int kk = c * BK;
        const int total = 1024 + NT * 8;
        for (int t = tid; t < total; t += 256) {
            if (t < 1024) {
                if (AFP32) {
                    int r = t >> 3, s = t & 7;
                    int gr = bm + r; if (gr >= M) gr = M - 1;
                    const float* src = Af + (size_t)gr * KTOT + kk + s * 4;
                    uint32_t dst = smu + b * STAGE + r * 128 + ((s ^ (r & 7)) << 4);
                    CP_ASYNC16(dst, src);
                } else {
                    int split = t >> 9, idx = t & 511, r = idx >> 2, seg = idx & 3;
                    int gr = bm + r; if (gr >= M) gr = M - 1;
                    const __nv_bfloat16* src = (split ? Alo : Ahi) + (size_t)gr * KTOT + kk + seg * 8;
                    uint32_t dst = smu + b * STAGE + (split ? AL : AH) + r * 80 + seg * 16;
                    CP_ASYNC16(dst, src);
                }
            } else {
                int j = t - 1024;
                int split = (j >= NT * 4);
                int idx = split ? j - NT * 4 : j;
                int r = idx >> 2, seg = idx & 3;
                const __nv_bfloat16* src = (split ? Blo : Bhi) + (size_t)(bn + r) * KTOT + kk + seg * 8;
                uint32_t dst = smu + b * STAGE + (split ? BL : BH) + r * 80 + seg * 16;
                CP_ASYNC16(dst, src);
            }
        }
    };

    auto compute = [&](int b) {
        const uint32_t pb = smu + b * STAGE;
        const char* pc = sm + (size_t)b * STAGE;
#pragma unroll
        for (int ks = 0; ks < 2; ks++) {
            const int kbyte = ks * 32;
            uint32_t ah[2][4], al[2][4];
            if (AFP32) {
#pragma unroll
                for (int mt = 0; mt < 2; mt++) {
#pragma unroll
                    for (int j = 0; j < 4; j++) {
                        int row = wm * 32 + mt * 16 + g + ((j & 1) << 3);
                        int s = (tig >> 1) + ((j >> 1) << 1) + (ks << 2);
                        int h = tig & 1;
                        const float2 f = *(const float2*)(pc + row * 128 + ((s ^ g) << 4) + (h << 3));
                        uint32_t hi_ = cvt_bf16x2(f.y, f.x);
                        float h0 = __uint_as_float(hi_ << 16);
                        float h1 = __uint_as_float(hi_ & 0xffff0000u);
                        uint32_t lo_ = cvt_bf16x2(f.y - h1, f.x - h0);
                        ah[mt][j] = hi_;
                        al[mt][j] = lo_;
                    }
                }
            } else {
#pragma unroll
                for (int t = 0; t < 2; t++) {
                    uint32_t aoff = (uint32_t)(wm * 32 + t * 16 + a_lr) * 80 + kbyte + a_seg * 16;
                    ldsm_x4(ah[t], pb + AH + aoff);
                    ldsm_x4(al[t], pb + AL + aoff);
                }
            }
            uint32_t bhf[NFW * 2], blf[NFW * 2];
#pragma unroll
            for (int f2 = 0; f2 < NFW / 2; f2++) {
                uint32_t boff = (uint32_t)(wn * (NT / 2) + f2 * 16 + b_row) * 80 + kbyte + b_seg * 16;
                ldsm_x4(&bhf[f2 * 4], pb + BH + boff);
                ldsm_x4(&blf[f2 * 4], pb + BL + boff);
            }
            if (NFW & 1) {
                uint32_t boff = (uint32_t)(wn * (NT / 2) + (NFW - 1) * 8 + b2_row) * 80 + kbyte + b2_seg * 16;
                ldsm_x2(&bhf[(NFW - 1) * 2], pb + BH + boff);
                ldsm_x2(&blf[(NFW - 1) * 2], pb + BL + boff);
            }
#pragma unroll
            for (int f = 0; f < NFW; f++) {
#pragma unroll
                for (int t = 0; t < 2; t++) {
                    mma_bf16(acc[t][f], ah[t], &bhf[f * 2]);
                    mma_bf16(acc[t][f], ah[t], &blf[f * 2]);
                    mma_bf16(acc[t][f], al[t], &bhf[f * 2]);
                }
            }
        }
    };

    stage(0, 0);
    CP_COMMIT();
    stage(1, 1);
    CP_COMMIT();
    for (int c = 0; c < NCH; c++) {
        if (c < NCH - 1) { CP_WAIT(1); } else { CP_WAIT(0); }
        __syncthreads();
        if (c + 2 < NCH) {
            stage(c + 2, (c + 2) % 3);
            CP_COMMIT();
        }
        compute(c % 3);
    }

#pragma unroll
    for (int t = 0; t < 2; t++) {
        const int row0 = bm + wm * 32 + t * 16 + g;
        const int row1 = row0 + 8;
#pragma unroll
        for (int f = 0; f < NFW; f++) {
            const int col = bn + wn * (NT / 2) + f * 8 + tig * 2;
            if (row0 < M) {
                float2 v = {acc[t][f][0], acc[t][f][1]};
                *(float2*)(Cout + (size_t)row0 * NTOT + col) = v;
            }
            if (row1 < M) {
                float2 v = {acc[t][f][2], acc[t][f][3]};
                *(float2*)(Cout + (size_t)row1 * NTOT + col) = v;
            }
        }
    }
}

__global__ void __launch_bounds__(256, 2)
k_gemm1_mma(const float* __restrict__ x) {
    gemm_mma_body<HDIM, 128, IN_C, true>(x, nullptr, nullptr, g_w1t_hi, g_w1t_lo, g_h1, N_NODES);
}
__global__ void __launch_bounds__(256, 2)
k_gemm2_mma() {
    gemm_mma_body<H2DIM, 80, HDIM, false>(nullptr, g_a1_hi, g_a1_lo, g_w2t_hi, g_w2t_lo, g_h2, N_NODES);
}

// ---------------------------------------------------------------------------
// Attention: one warp per destination node, online segment-softmax.
// Edge loop processed in PAIRS (2-wide): both gathers in flight (MLP 4) —
// measured optimum; 4-wide regresses via register-tier occupancy loss.
// ---------------------------------------------------------------------------
template <int CTOT, int VPL>
__device__ __forceinline__ void attn_load(const float* __restrict__ h,
                                          int node, int lane, float* xj) {
    if (VPL == 8) {
        const float4* p = (const float4*)(h + (size_t)node * CTOT + lane * 8);
        float4 a = p[0], b = p[1];
        xj[0] = a.x; xj[1] = a.y; xj[2] = a.z; xj[3] = a.w;
        xj[4] = b.x; xj[5] = b.y; xj[6] = b.z; xj[7] = b.w;
    } else {
        const float* jb = h + (size_t)node * CTOT + lane * VPL;
#pragma unroll
        for (int k = 0; k < VPL; k++) xj[k] = jb[k];
    }
}

template <int CTOT, int VPL, bool FINAL>
__device__ __forceinline__ void attn_body(const float* __restrict__ h,
                                          const float* __restrict__ bias,
                                          float* __restrict__ out) {
    int gw   = (blockIdx.x * blockDim.x + threadIdx.x) >> 5;
    int lane = threadIdx.x & 31;
    if (gw >= N_NODES) return;

    float xi[VPL];
    attn_load<CTOT, VPL>(h, gw, lane, xi);

    float m = -1e30f, s = 0.f;
    float acc[VPL];
#pragma unroll
    for (int k = 0; k < VPL; k++) acc[k] = 0.f;

    const int e0 = g_rowptr[gw], e1 = g_rowptr[gw + 1];
    int e = e0;
    for (; e + 1 < e1; e += 2) {
        int s0 = g_csrsrc[e];
        int s1 = g_csrsrc[e + 1];
        float xj0[VPL], xj1[VPL];
        attn_load<CTOT, VPL>(h, s0, lane, xj0);
        attn_load<CTOT, VPL>(h, s1, lane, xj1);
        float d0 = 0.f, d1 = 0.f;
#pragma unroll
        for (int k = 0; k < VPL; k++) { d0 = fmaf(xi[k], xj0[k], d0); d1 = fmaf(xi[k], xj1[k], d1); }
        d0 += __shfl_xor_sync(0xffffffffu, d0, 1);
        d1 += __shfl_xor_sync(0xffffffffu, d1, 1);
        d0 += __shfl_xor_sync(0xffffffffu, d0, 2);
        d1 += __shfl_xor_sync(0xffffffffu, d1, 2);
        d0 += __shfl_xor_sync(0xffffffffu, d0, 4);
        d1 += __shfl_xor_sync(0xffffffffu, d1, 4);
        {
            float a = d0 > 0.f ? d0 : 0.2f * d0;
            float mn = fmaxf(m, a);
            float corr = __expf(m - mn);
            float wgt = __expf(a - mn);
            s = s * corr + wgt;
#pragma unroll
            for (int k = 0; k < VPL; k++) acc[k] = fmaf(acc[k], corr, wgt * xj0[k]);
            m = mn;
        }
        {
            float a = d1 > 0.f ? d1 : 0.2f * d1;
            float mn = fmaxf(m, a);
            float corr = __expf(m - mn);
            float wgt = __expf(a - mn);
            s = s * corr + wgt;
#pragma unroll
            for (int k = 0; k < VPL; k++) acc[k] = fmaf(acc[k], corr, wgt * xj1[k]);
            m = mn;
        }
    }
    if (e < e1) {
        int s0 = g_csrsrc[e];
        float xj0[VPL];
        attn_load<CTOT, VPL>(h, s0, lane, xj0);
        float d0 = 0.f;
#pragma unroll
        for (int k = 0; k < VPL; k++) d0 = fmaf(xi[k], xj0[k], d0);
        d0 += __shfl_xor_sync(0xffffffffu, d0, 1);
        d0 += __shfl_xor_sync(0xffffffffu, d0, 2);
        d0 += __shfl_xor_sync(0xffffffffu, d0, 4);
        float a = d0 > 0.f ? d0 : 0.2f * d0;
        float mn = fmaxf(m, a);
        float corr = __expf(m - mn);
        float wgt = __expf(a - mn);
        s = s * corr + wgt;
#pragma unroll
        for (int k = 0; k < VPL; k++) acc[k] = fmaf(acc[k], corr, wgt * xj0[k]);
        m = mn;
    }
    float inv = 1.f / (s + 1e-16f);

    if (!FINAL) {
#pragma unroll
        for (int k = 0; k < VPL; k++) {
            float v = acc[k] * inv + bias[lane * VPL + k];
            v = v > 0.f ? v : expm1f(v);
            size_t idx = (size_t)gw * CTOT + lane * VPL + k;
            __nv_bfloat16 hh = __float2bfloat16(v);
            g_a1_hi[idx] = hh;
            g_a1_lo[idx] = __float2bfloat16(v - __bfloat162float(hh));
        }
    } else {
        float r[VPL];
#pragma unroll
        for (int k = 0; k < VPL; k++) r[k] = acc[k] * inv;
#pragma unroll
        for (int k = 0; k < VPL; k++) r[k] += __shfl_down_sync(0xffffffffu, r[k], 16);
#pragma unroll
        for (int k = 0; k < VPL; k++) r[k] += __shfl_down_sync(0xffffffffu, r[k], 8);
        float v[VPL];
        float mx = -1e30f;
        if (lane < 8) {
#pragma unroll
            for (int k = 0; k < VPL; k++) {
                v[k] = 0.25f * r[k] + bias[lane * VPL + k];
                mx = fmaxf(mx, v[k]);
            }
        }
        mx = fmaxf(mx, __shfl_xor_sync(0xffffffffu, mx, 1));
        mx = fmaxf(mx, __shfl_xor_sync(0xffffffffu, mx, 2));
        mx = fmaxf(mx, __shfl_xor_sync(0xffffffffu, mx, 4));
        float se = 0.f;
        if (lane < 8) {
#pragma unroll
            for (int k = 0; k < VPL; k++) se += __expf(v[k] - mx);
        }
        se += __shfl_xor_sync(0xffffffffu, se, 1);
        se += __shfl_xor_sync(0xffffffffu, se, 2);
        se += __shfl_xor_sync(0xffffffffu, se, 4);
        float lse = logf(se) + mx;
        if (lane < 8) {
#pragma unroll
            for (int k = 0; k < VPL; k++)
                out[(size_t)gw * OUT_C + lane * VPL + k] = v[k] - lse;
        }
    }
}

__global__ void k_attn1(const float* __restrict__ b1) {
    attn_body<HDIM, 8, false>(g_h1, b1, nullptr);
}
__global__ void k_attn2(const float* __restrict__ b2, float* __restrict__ out) {
    attn_body<H2DIM, 5, true>(g_h2, b2, out);
}

// ---------------------------------------------------------------------------
// Launch: CSR build forked onto a side stream, overlapping gemm1 (R13 layout).
// ---------------------------------------------------------------------------
extern "C" void kernel_launch(void* const* d_in, const int* in_sizes, int n_in,
                              void* d_out, int out_size) {
    const float* x  = (const float*)d_in[0];
    const int*   ei = (const int*)d_in[1];
    const float* W1 = (const float*)d_in[2];
    const float* b1 = (const float*)d_in[3];
    const float* W2 = (const float*)d_in[4];
    const float* b2 = (const float*)d_in[5];
    float* out = (float*)d_out;
    int E = in_sizes[1] / 2;

    const int SMEM1 = 3 * (16384 + 128 * 160);   // 110592 (x2 CTAs/SM)
    const int SMEM2 = 3 * (20480 + 80 * 160);    // 99840  (x2 CTAs/SM)
    cudaFuncSetAttribute(k_gemm1_mma, cudaFuncAttributeMaxDynamicSharedMemorySize, SMEM1);
    cudaFuncSetAttribute(k_gemm2_mma, cudaFuncAttributeMaxDynamicSharedMemorySize, SMEM2);

    static cudaStream_t s_side = nullptr;
    static cudaEvent_t  s_fork = nullptr, s_join = nullptr;
    if (s_side == nullptr) {
        cudaStreamCreateWithFlags(&s_side, cudaStreamNonBlocking);
        cudaEventCreateWithFlags(&s_fork, cudaEventDisableTiming);
        cudaEventCreateWithFlags(&s_join, cudaEventDisableTiming);
    }

    // main: weight prep (gemm1 dependency)
    k_prep_w<<<(IN_C * HDIM + HDIM * H2DIM + 255) / 256, 256>>>(W1, W2);

    // fork: CSR build beside gemm1
    cudaEventRecord(s_fork, 0);
    cudaStreamWaitEvent(s_side, s_fork, 0);
    k_init_cnt<<<(N_NODES + 255) / 256, 256, 0, s_side>>>(out, out_size);
    k_hist<<<(E + 255) / 256, 256, 0, s_side>>>(ei, E);
    k_scan<<<1, 1024, 0, s_side>>>(N_NODES);
    k_scatter<<<(E + N_NODES + 255) / 256, 256, 0, s_side>>>(ei, E);
    cudaEventRecord(s_join, s_side);

    // main: gemm1 concurrent with CSR
    k_gemm1_mma<<<dim3(2, MBLK), 256, SMEM1>>>(x);

    // join: attn1 needs both gemm1 (main) and CSR (side)
    cudaStreamWaitEvent(0, s_join, 0);
    k_attn1<<<(N_NODES + 7) / 8, 256>>>(b1);
    k_gemm2_mma<<<dim3(2, MBLK), 256, SMEM2>>>();
    k_attn2<<<(N_NODES + 7) / 8, 256>>>(b2, out);
}

// round 17
// speedup vs baseline: 1.1214x; 1.0423x over previous
#include <cuda_runtime.h>
#include <cuda_bf16.h>
#include <math.h>
#include <stdint.h>

// Problem constants
#define N_NODES 50000
#define IN_C    512
#define HDIM    256   // H*HID
#define H2DIM   160   // H*OUT_C
#define OUT_C   40
#define MAXE    400000
#define MBLK    391   // ceil(50000/128)
#define PERSIST 304   // 152 SMs x 2 CTAs

// ---------------------------------------------------------------------------
// Scratch (static device globals)
// ---------------------------------------------------------------------------
__device__ float g_h1[(size_t)N_NODES * HDIM];
__device__ float g_h2[(size_t)N_NODES * H2DIM];
__device__ __align__(16) __nv_bfloat16 g_a1_hi[(size_t)N_NODES * HDIM];
__device__ __align__(16) __nv_bfloat16 g_a1_lo[(size_t)N_NODES * HDIM];
__device__ __align__(16) __nv_bfloat16 g_w1t_hi[(size_t)HDIM * IN_C];   // [n][k]
__device__ __align__(16) __nv_bfloat16 g_w1t_lo[(size_t)HDIM * IN_C];
__device__ __align__(16) __nv_bfloat16 g_w2t_hi[(size_t)H2DIM * HDIM];  // [n][k]
__device__ __align__(16) __nv_bfloat16 g_w2t_lo[(size_t)H2DIM * HDIM];
__device__ int g_cnt[N_NODES];
__device__ int g_rowptr[N_NODES + 1];
__device__ int g_wptr[N_NODES];
__device__ int g_csrsrc[MAXE + N_NODES];

// ---------------------------------------------------------------------------
// mma.sync bf16 + ldmatrix + cp.async helpers (family-common ISA)
// ---------------------------------------------------------------------------
__device__ __forceinline__ void mma_bf16(float* d, const uint32_t* a, const uint32_t* b) {
    asm volatile(
        "mma.sync.aligned.m16n8k16.row.col.f32.bf16.bf16.f32 "
        "{%0,%1,%2,%3}, {%4,%5,%6,%7}, {%8,%9}, {%0,%1,%2,%3};"
        : "+f"(d[0]), "+f"(d[1]), "+f"(d[2]), "+f"(d[3])
        : "r"(a[0]), "r"(a[1]), "r"(a[2]), "r"(a[3]), "r"(b[0]), "r"(b[1]));
}
__device__ __forceinline__ void ldsm_x4(uint32_t* r, uint32_t addr) {
    asm volatile("ldmatrix.sync.aligned.m8n8.x4.shared.b16 {%0,%1,%2,%3}, [%4];"
        : "=r"(r[0]), "=r"(r[1]), "=r"(r[2]), "=r"(r[3]) : "r"(addr));
}
__device__ __forceinline__ void ldsm_x2(uint32_t* r, uint32_t addr) {
    asm volatile("ldmatrix.sync.aligned.m8n8.x2.shared.b16 {%0,%1}, [%2];"
        : "=r"(r[0]), "=r"(r[1]) : "r"(addr));
}
__device__ __forceinline__ uint32_t smem_u32(const void* p) {
    uint32_t a;
    asm("{ .reg .u64 t; cvta.to.shared.u64 t, %1; cvt.u32.u64 %0, t; }" : "=r"(a) : "l"(p));
    return a;
}
#define CP_ASYNC16(dst, src) \
    asm volatile("cp.async.cg.shared.global [%0], [%1], 16;" :: "r"(dst), "l"(src))
#define CP_COMMIT()  asm volatile("cp.async.commit_group;" ::: "memory")
#define CP_WAIT(n)   asm volatile("cp.async.wait_group %0;" :: "n"(n) : "memory")

__device__ __forceinline__ uint32_t cvt_bf16x2(float hi_elem, float lo_elem) {
    uint32_t r;
    asm("cvt.rn.bf16x2.f32 %0, %1, %2;" : "=r"(r) : "f"(hi_elem), "f"(lo_elem));
    return r;
}

// ---------------------------------------------------------------------------
// Fused weight prep: transpose + bf16 split for W1 and W2 in one launch.
// ---------------------------------------------------------------------------
__global__ void k_prep_w(const float* __restrict__ W1, const float* __restrict__ W2) {
    int idx = blockIdx.x * blockDim.x + threadIdx.x;
    const int N1 = IN_C * HDIM;
    if (idx < N1) {
        int k = idx / HDIM, n = idx % HDIM;
        float v = W1[idx];
        __nv_bfloat16 h = __float2bfloat16(v);
        g_w1t_hi[(size_t)n * IN_C + k] = h;
        g_w1t_lo[(size_t)n * IN_C + k] = __float2bfloat16(v - __bfloat162float(h));
    } else if (idx < N1 + HDIM * H2DIM) {
        int j = idx - N1;
        int k = j / H2DIM, n = j % H2DIM;
        float v = W2[j];
        __nv_bfloat16 h = __float2bfloat16(v);
        g_w2t_hi[(size_t)n * HDIM + k] = h;
        g_w2t_lo[(size_t)n * HDIM + k] = __float2bfloat16(v - __bfloat162float(h));
    }
}

// ---------------------------------------------------------------------------
// CSR construction (+ output tail zeroing folded into init)
// ---------------------------------------------------------------------------
__global__ void k_init_cnt(float* out, int out_size) {
    int i = blockIdx.x * blockDim.x + threadIdx.x;
    if (i < N_NODES) g_cnt[i] = 1;
    if (blockIdx.x == 0) {
        for (int j = N_NODES * OUT_C + threadIdx.x; j < out_size; j += blockDim.x)
            out[j] = 0.f;
    }
}
__global__ void k_hist(const int* __restrict__ ei, int E) {
    int e = blockIdx.x * blockDim.x + threadIdx.x;
    if (e < E) {
        int d = ei[E + e];
        if ((unsigned)d < (unsigned)N_NODES) atomicAdd(&g_cnt[d], 1);
    }
}

__global__ void k_scan(int n) {
    __shared__ int wsum[32];
    __shared__ int s_carry;
    const int tid = threadIdx.x;
    const int lane = tid & 31, wrp = tid >> 5;
    if (tid == 0) s_carry = 0;
    __syncthreads();
    for (int base = 0; base < n; base += 8192) {
        int i0 = base + tid * 8;
        int v[8], run = 0;
#pragma unroll
        for (int j = 0; j < 8; j++) {
            int vi = (i0 + j < n) ? g_cnt[i0 + j] : 0;
            v[j] = run;
            run += vi;
        }
        int inc = run;
#pragma unroll
        for (int d = 1; d < 32; d <<= 1) {
            int t = __shfl_up_sync(0xffffffffu, inc, d);
            if (lane >= d) inc += t;
        }
        if (lane == 31) wsum[wrp] = inc;
        int carry_in = s_carry;
        __syncthreads();
        if (wrp == 0) {
            int wv = wsum[lane];
            int wi = wv;
#pragma unroll
            for (int d = 1; d < 32; d <<= 1) {
                int t = __shfl_up_sync(0xffffffffu, wi, d);
                if (lane >= d) wi += t;
            }
            wsum[lane] = wi - wv;
            if (lane == 31) s_carry = carry_in + wi;
        }
        __syncthreads();
        int thr_excl = carry_in + wsum[wrp] + (inc - run);
#pragma unroll
        for (int j = 0; j < 8; j++) {
            int i = i0 + j;
            if (i < n) { g_rowptr[i] = thr_excl + v[j]; g_wptr[i] = thr_excl + v[j]; }
        }
        __syncthreads();
    }
    if (tid == 0) g_rowptr[n] = s_carry;
}

__global__ void k_scatter(const int* __restrict__ ei, int E) {
    int e = blockIdx.x * blockDim.x + threadIdx.x;
    int total = E + N_NODES;
    if (e >= total) return;
    int s, d;
    if (e < E) { s = ei[e]; d = ei[E + e]; }
    else       { s = d = e - E; }
    if ((unsigned)d >= (unsigned)N_NODES || (unsigned)s >= (unsigned)N_NODES) return;
    int pos = atomicAdd(&g_wptr[d], 1);
    if ((unsigned)pos < (unsigned)(MAXE + N_NODES)) g_csrsrc[pos] = s;
}

// ---------------------------------------------------------------------------
// PERSISTENT triple-buffered cp.async mma GEMM. 256 threads = 8 warps
// (4M x 2N), two CTAs per SM. Each CTA loops over tiles (tile += gridDim.x)
// so there is no wave-quantization tail. 2 n-blocks per M-block.
// AFP32: A staged raw fp32 (seg-swizzled), split to bf16 hi/lo at frag load.
// ---------------------------------------------------------------------------
template <int NTOT, int NT, int KTOT, bool AFP32>
__device__ __forceinline__ void gemm_mma_body(const float* __restrict__ Af,
                                              const __nv_bfloat16* __restrict__ Ahi,
                                              const __nv_bfloat16* __restrict__ Alo,
                                              const __nv_bfloat16* __restrict__ Bhi,
                                              const __nv_bfloat16* __restrict__ Blo,
                                              float* __restrict__ Cout, int M) {
    constexpr int BK  = 32;
    constexpr int NCH = KTOT / BK;
    constexpr int NFW = NT / 16;
    constexpr int AH = 0;
    constexpr int AL = 10240;
    constexpr int BH = AFP32 ? 16384 : 20480;
    constexpr int BL = BH + NT * 80;
    constexpr int STAGE = BH + NT * 160;
    const int NTILES = 2 * MBLK;

    extern __shared__ char sm[];
    const uint32_t smu = smem_u32(sm);

    const int tid  = threadIdx.x;
    const int w    = tid >> 5;
    const int lane = tid & 31;
    const int g    = lane >> 2;
    const int tig  = lane & 3;
    const int wm   = w & 3;
    const int wn   = w >> 2;

    const int a_lr   = lane & 15;
    const int a_seg  = lane >> 4;
    const int b_row  = (lane & 7) + ((lane >> 4) << 3);
    const int b_seg  = (lane >> 3) & 1;
    const int b2_row = lane & 7;
    const int b2_seg = (lane >> 3) & 1;

    for (int tile = blockIdx.x; tile < NTILES; tile += gridDim.x) {
        const int bm = (tile >> 1) * 128;
        const int bn = (tile & 1) * NT;

        float acc[2][NFW][4];
#pragma unroll
        for (int t = 0; t < 2; t++)
#pragma unroll
            for (int f = 0; f < NFW; f++)
#pragma unroll
                for (int q = 0; q < 4; q++) acc[t][f][q] = 0.f;

        auto stage = [&](int c, int b) {
            const int kk = c * BK;
            const int total = 1024 + NT * 8;
            for (int t = tid; t < total; t += 256) {
                if (t < 1024) {
                    if (AFP32) {
                        int r = t >> 3, s = t & 7;
                        int gr = bm + r; if (gr >= M) gr = M - 1;
                        const float* src = Af + (size_t)gr * KTOT + kk + s * 4;
                        uint32_t dst = smu + b * STAGE + r * 128 + ((s ^ (r & 7)) << 4);
                        CP_ASYNC16(dst, src);
                    } else {
                        int split = t >> 9, idx = t & 511, r = idx >> 2, seg = idx & 3;
                        int gr = bm + r; if (gr >= M) gr = M - 1;
                        const __nv_bfloat16* src = (split ? Alo : Ahi) + (size_t)gr * KTOT + kk + seg * 8;
                        uint32_t dst = smu + b * STAGE + (split ? AL : AH) + r * 80 + seg * 16;
                        CP_ASYNC16(dst, src);
                    }
                } else {
                    int j = t - 1024;
                    int split = (j >= NT * 4);
                    int idx = split ? j - NT * 4 : j;
                    int r = idx >> 2, seg = idx & 3;
                    const __nv_bfloat16* src = (split ? Blo : Bhi) + (size_t)(bn + r) * KTOT + kk + seg * 8;
                    uint32_t dst = smu + b * STAGE + (split ? BL : BH) + r * 80 + seg * 16;
                    CP_ASYNC16(dst, src);
                }
            }
        };

        auto compute = [&](int b) {
            const uint32_t pb = smu + b * STAGE;
            const char* pc = sm + (size_t)b * STAGE;
#pragma unroll
            for (int ks = 0; ks < 2; ks++) {
                const int kbyte = ks * 32;
                uint32_t ah[2][4], al[2][4];
                if (AFP32) {
#pragma unroll
                    for (int mt = 0; mt < 2; mt++) {
#pragma unroll
                        for (int j = 0; j < 4; j++) {
                            int row = wm * 32 + mt * 16 + g + ((j & 1) << 3);
                            int s = (tig >> 1) + ((j >> 1) << 1) + (ks << 2);
                            int h = tig & 1;
                            const float2 f = *(const float2*)(pc + row * 128 + ((s ^ g) << 4) + (h << 3));
                            uint32_t hi_ = cvt_bf16x2(f.y, f.x);
                            float h0 = __uint_as_float(hi_ << 16);
                            float h1 = __uint_as_float(hi_ & 0xffff0000u);
                            uint32_t lo_ = cvt_bf16x2(f.y - h1, f.x - h0);
                            ah[mt][j] = hi_;
                            al[mt][j] = lo_;
                        }
                    }
                } else {
#pragma unroll
                    for (int t = 0; t < 2; t++) {
                        uint32_t aoff = (uint32_t)(wm * 32 + t * 16 + a_lr) * 80 + kbyte + a_seg * 16;
                        ldsm_x4(ah[t], pb + AH + aoff);
                        ldsm_x4(al[t], pb + AL + aoff);
                    }
                }
                uint32_t bhf[NFW * 2], blf[NFW * 2];
#pragma unroll
                for (int f2 = 0; f2 < NFW / 2; f2++) {
                    uint32_t boff = (uint32_t)(wn * (NT / 2) + f2 * 16 + b_row) * 80 + kbyte + b_seg * 16;
                    ldsm_x4(&bhf[f2 * 4], pb + BH + boff);
                    ldsm_x4(&blf[f2 * 4], pb + BL + boff);
                }
                if (NFW & 1) {
                    uint32_t boff = (uint32_t)(wn * (NT / 2) + (NFW - 1) * 8 + b2_row) * 80 + kbyte + b2_seg * 16;
                    ldsm_x2(&bhf[(NFW - 1) * 2], pb + BH + boff);
                    ldsm_x2(&blf[(NFW - 1) * 2], pb + BL + boff);
                }
#pragma unroll
                for (int f = 0; f < NFW; f++) {
#pragma unroll
                    for (int t = 0; t < 2; t++) {
                        mma_bf16(acc[t][f], ah[t], &bhf[f * 2]);
                        mma_bf16(acc[t][f], ah[t], &blf[f * 2]);
                        mma_bf16(acc[t][f], al[t], &bhf[f * 2]);
                    }
                }
            }
        };

        stage(0, 0);
        CP_COMMIT();
        stage(1, 1);
        CP_COMMIT();
        for (int c = 0; c < NCH; c++) {
            if (c < NCH - 1) { CP_WAIT(1); } else { CP_WAIT(0); }
            __syncthreads();
            if (c + 2 < NCH) {
                stage(c + 2, (c + 2) % 3);
                CP_COMMIT();
            }
            compute(c % 3);
        }

        // epilogue
#pragma unroll
        for (int t = 0; t < 2; t++) {
            const int row0 = bm + wm * 32 + t * 16 + g;
            const int row1 = row0 + 8;
#pragma unroll
            for (int f = 0; f < NFW; f++) {
                const int col = bn + wn * (NT / 2) + f * 8 + tig * 2;
                if (row0 < M) {
                    float2 v = {acc[t][f][0], acc[t][f][1]};
                    *(float2*)(Cout + (size_t)row0 * NTOT + col) = v;
                }
                if (row1 < M) {
                    float2 v = {acc[t][f][2], acc[t][f][3]};
                    *(float2*)(Cout + (size_t)row1 * NTOT + col) = v;
                }
            }
        }
        // all warps must finish reading buffers before the next tile restages
        __syncthreads();
    }
}

__global__ void __launch_bounds__(256, 2)
k_gemm1_mma(const float* __restrict__ x) {
    gemm_mma_body<HDIM, 128, IN_C, true>(x, nullptr, nullptr, g_w1t_hi, g_w1t_lo, g_h1, N_NODES);
}
__global__ void __launch_bounds__(256, 2)
k_gemm2_mma() {
    gemm_mma_body<H2DIM, 80, HDIM, false>(nullptr, g_a1_hi, g_a1_lo, g_w2t_hi, g_w2t_lo, g_h2, N_NODES);
}

// ---------------------------------------------------------------------------
// Attention: one warp per destination node, online segment-softmax.
// Edge loop processed in PAIRS (2-wide): measured optimum.
// ---------------------------------------------------------------------------
template <int CTOT, int VPL>
__device__ __forceinline__ void attn_load(const float* __restrict__ h,
                                          int node, int lane, float* xj) {
    if (VPL == 8) {
        const float4* p = (const float4*)(h + (size_t)node * CTOT + lane * 8);
        float4 a = p[0], b = p[1];
        xj[0] = a.x; xj[1] = a.y; xj[2] = a.z; xj[3] = a.w;
        xj[4] = b.x; xj[5] = b.y; xj[6] = b.z; xj[7] = b.w;
    } else {
        const float* jb = h + (size_t)node * CTOT + lane * VPL;
#pragma unroll
        for (int k = 0; k < VPL; k++) xj[k] = jb[k];
    }
}

template <int CTOT, int VPL, bool FINAL>
__device__ __forceinline__ void attn_body(const float* __restrict__ h,
                                          const float* __restrict__ bias,
                                          float* __restrict__ out) {
    int gw   = (blockIdx.x * blockDim.x + threadIdx.x) >> 5;
    int lane = threadIdx.x & 31;
    if (gw >= N_NODES) return;

    float xi[VPL];
    attn_load<CTOT, VPL>(h, gw, lane, xi);

    float m = -1e30f, s = 0.f;
    float acc[VPL];
#pragma unroll
    for (int k = 0; k < VPL; k++) acc[k] = 0.f;

    const int e0 = g_rowptr[gw], e1 = g_rowptr[gw + 1];
    int e = e0;
    for (; e + 1 < e1; e += 2) {
        int s0 = g_csrsrc[e];
        int s1 = g_csrsrc[e + 1];
        float xj0[VPL], xj1[VPL];
        attn_load<CTOT, VPL>(h, s0, lane, xj0);
        attn_load<CTOT, VPL>(h, s1, lane, xj1);
        float d0 = 0.f, d1 = 0.f;
#pragma unroll
        for (int k = 0; k < VPL; k++) { d0 = fmaf(xi[k], xj0[k], d0); d1 = fmaf(xi[k], xj1[k], d1); }
        d0 += __shfl_xor_sync(0xffffffffu, d0, 1);
        d1 += __shfl_xor_sync(0xffffffffu, d1, 1);
        d0 += __shfl_xor_sync(0xffffffffu, d0, 2);
        d1 += __shfl_xor_sync(0xffffffffu, d1, 2);
        d0 += __shfl_xor_sync(0xffffffffu, d0, 4);
        d1 += __shfl_xor_sync(0xffffffffu, d1, 4);
        {
            float a = d0 > 0.f ? d0 : 0.2f * d0;
            float mn = fmaxf(m, a);
            float corr = __expf(m - mn);
            float wgt = __expf(a - mn);
            s = s * corr + wgt;
#pragma unroll
            for (int k = 0; k < VPL; k++) acc[k] = fmaf(acc[k], corr, wgt * xj0[k]);
            m = mn;
        }
        {
            float a = d1 > 0.f ? d1 : 0.2f * d1;
            float mn = fmaxf(m, a);
            float corr = __expf(m - mn);
            float wgt = __expf(a - mn);
            s = s * corr + wgt;
#pragma unroll
            for (int k = 0; k < VPL; k++) acc[k] = fmaf(acc[k], corr, wgt * xj1[k]);
            m = mn;
        }
    }
    if (e < e1) {
        int s0 = g_csrsrc[e];
        float xj0[VPL];
        attn_load<CTOT, VPL>(h, s0, lane, xj0);
        float d0 = 0.f;
#pragma unroll
        for (int k = 0; k < VPL; k++) d0 = fmaf(xi[k], xj0[k], d0);
        d0 += __shfl_xor_sync(0xffffffffu, d0, 1);
        d0 += __shfl_xor_sync(0xffffffffu, d0, 2);
        d0 += __shfl_xor_sync(0xffffffffu, d0, 4);
        float a = d0 > 0.f ? d0 : 0.2f * d0;
        float mn = fmaxf(m, a);
        float corr = __expf(m - mn);
        float wgt = __expf(a - mn);
        s = s * corr + wgt;
#pragma unroll
        for (int k = 0; k < VPL; k++) acc[k] = fmaf(acc[k], corr, wgt * xj0[k]);
        m = mn;
    }
    float inv = 1.f / (s + 1e-16f);

    if (!FINAL) {
#pragma unroll
        for (int k = 0; k < VPL; k++) {
            float v = acc[k] * inv + bias[lane * VPL + k];
            v = v > 0.f ? v : expm1f(v);
            size_t idx = (size_t)gw * CTOT + lane * VPL + k;
            __nv_bfloat16 hh = __float2bfloat16(v);
            g_a1_hi[idx] = hh;
            g_a1_lo[idx] = __float2bfloat16(v - __bfloat162float(hh));
        }
    } else {
        float r[VPL];
#pragma unroll
        for (int k = 0; k < VPL; k++) r[k] = acc[k] * inv;
#pragma unroll
        for (int k = 0; k < VPL; k++) r[k] += __shfl_down_sync(0xffffffffu, r[k], 16);
#pragma unroll
        for (int k = 0; k < VPL; k++) r[k] += __shfl_down_sync(0xffffffffu, r[k], 8);
        float v[VPL];
        float mx = -1e30f;
        if (lane < 8) {
#pragma unroll
            for (int k = 0; k < VPL; k++) {
                v[k] = 0.25f * r[k] + bias[lane * VPL + k];
                mx = fmaxf(mx, v[k]);
            }
        }
        mx = fmaxf(mx, __shfl_xor_sync(0xffffffffu, mx, 1));
        mx = fmaxf(mx, __shfl_xor_sync(0xffffffffu, mx, 2));
        mx = fmaxf(mx, __shfl_xor_sync(0xffffffffu, mx, 4));
        float se = 0.f;
        if (lane < 8) {
#pragma unroll
            for (int k = 0; k < VPL; k++) se += __expf(v[k] - mx);
        }
        se += __shfl_xor_sync(0xffffffffu, se, 1);
        se += __shfl_xor_sync(0xffffffffu, se, 2);
        se += __shfl_xor_sync(0xffffffffu, se, 4);
        float lse = logf(se) + mx;
        if (lane < 8) {
#pragma unroll
            for (int k = 0; k < VPL; k++)
                out[(size_t)gw * OUT_C + lane * VPL + k] = v[k] - lse;
        }
    }
}

__global__ void k_attn1(const float* __restrict__ b1) {
    attn_body<HDIM, 8, false>(g_h1, b1, nullptr);
}
__global__ void k_attn2(const float* __restrict__ b2, float* __restrict__ out) {
    attn_body<H2DIM, 5, true>(g_h2, b2, out);
}

// ---------------------------------------------------------------------------
// Launch: CSR build forked onto a side stream, overlapping gemm1.
// Persistent GEMM grids (304 CTAs) remove wave-quantization tails.
// ---------------------------------------------------------------------------
extern "C" void kernel_launch(void* const* d_in, const int* in_sizes, int n_in,
                              void* d_out, int out_size) {
    const float* x  = (const float*)d_in[0];
    const int*   ei = (const int*)d_in[1];
    const float* W1 = (const float*)d_in[2];
    const float* b1 = (const float*)d_in[3];
    const float* W2 = (const float*)d_in[4];
    const float* b2 = (const float*)d_in[5];
    float* out = (float*)d_out;
    int E = in_sizes[1] / 2;

    const int SMEM1 = 3 * (16384 + 128 * 160);   // 110592 (x2 CTAs/SM)
    const int SMEM2 = 3 * (20480 + 80 * 160);    // 99840  (x2 CTAs/SM)
    cudaFuncSetAttribute(k_gemm1_mma, cudaFuncAttributeMaxDynamicSharedMemorySize, SMEM1);
    cudaFuncSetAttribute(k_gemm2_mma, cudaFuncAttributeMaxDynamicSharedMemorySize, SMEM2);

    static cudaStream_t s_side = nullptr;
    static cudaEvent_t  s_fork = nullptr, s_join = nullptr;
    if (s_side == nullptr) {
        cudaStreamCreateWithFlags(&s_side, cudaStreamNonBlocking);
        cudaEventCreateWithFlags(&s_fork, cudaEventDisableTiming);
        cudaEventCreateWithFlags(&s_join, cudaEventDisableTiming);
    }

    // main: weight prep (gemm1 dependency)
    k_prep_w<<<(IN_C * HDIM + HDIM * H2DIM + 255) / 256, 256>>>(W1, W2);

    // fork: CSR build beside gemm1
    cudaEventRecord(s_fork, 0);
    cudaStreamWaitEvent(s_side, s_fork, 0);
    k_init_cnt<<<(N_NODES + 255) / 256, 256, 0, s_side>>>(out, out_size);
    k_hist<<<(E + 255) / 256, 256, 0, s_side>>>(ei, E);
    k_scan<<<1, 1024, 0, s_side>>>(N_NODES);
    k_scatter<<<(E + N_NODES + 255) / 256, 256, 0, s_side>>>(ei, E);
    cudaEventRecord(s_join, s_side);

    // main: persistent gemm1 concurrent with CSR
    k_gemm1_mma<<<PERSIST, 256, SMEM1>>>(x);

    // join: attn1 needs both gemm1 (main) and CSR (side)
    cudaStreamWaitEvent(0, s_join, 0);
    k_attn1<<<(N_NODES + 7) / 8, 256>>>(b1);
    k_gemm2_mma<<<PERSIST, 256, SMEM2>>>();
    k_attn2<<<(N_NODES + 7) / 8, 256>>>(b2, out);
}